// round 3
// baseline (speedup 1.0000x reference)
#include <cuda_runtime.h>
#include <math.h>

#define NB 16
#define NT 2048
#define NC 2048
#define NH 256
#define BTOT (NB * NT)   // 32768 rows

// Scratch (device globals: allocation-free per harness rules)
__device__ float g_K[BTOT * NH];            // 33.5 MB
__device__ float g_Q[BTOT * NH];
__device__ float g_V[BTOT * NH];
__device__ float g_L[NB * NT * NT];         // 268 MB, L[b][j][i] = k_i . q_j * sqrt(C)
__device__ float g_m[BTOT];                 // per (b,j) column max
__device__ float g_rs[BTOT];                // per (b,j) 1/sum

// ---------------------------------------------------------------------------
// Kernel 1: projections  Out[M=BT][N=HS] = X[M][K=C] @ W[K][N]
// BM=128 BN=128 BK=16, 256 threads, 8x8 microtile, double-buffered SMEM.
// ---------------------------------------------------------------------------
__global__ void __launch_bounds__(256) proj_kernel(const float* __restrict__ X,
                                                   const float* __restrict__ W,
                                                   int which)
{
    float* Out = (which == 0) ? g_K : (which == 1) ? g_Q : g_V;
    const int BK = 16;
    __shared__ float As[2][BK][128];   // transposed: As[k][m]
    __shared__ float Bs[2][BK][128];   // Bs[k][n]

    const int tid = threadIdx.x;
    const int m0 = blockIdx.y * 128;
    const int n0 = blockIdx.x * 128;

    const int arow = tid >> 2;          // 0..63 (+64)
    const int acol = (tid & 3) << 2;    // 0,4,8,12
    const int brow = tid >> 5;          // 0..7 (+8)
    const int bcol = (tid & 31) << 2;   // 0..124
    const int tx = tid & 15, ty = tid >> 4;

    float acc[8][8];
#pragma unroll
    for (int i = 0; i < 8; i++)
#pragma unroll
        for (int j = 0; j < 8; j++) acc[i][j] = 0.f;

    // prologue: tile 0
    {
        const float* Xp = X + (size_t)m0 * NC;
#pragma unroll
        for (int it = 0; it < 2; it++) {
            int r = arow + it * 64;
            float4 v = *(const float4*)(Xp + (size_t)r * NC + acol);
            As[0][acol + 0][r] = v.x; As[0][acol + 1][r] = v.y;
            As[0][acol + 2][r] = v.z; As[0][acol + 3][r] = v.w;
        }
        const float* Wp = W + n0;
#pragma unroll
        for (int it = 0; it < 2; it++) {
            int r = brow + it * 8;
            *(float4*)&Bs[0][r][bcol] = *(const float4*)(Wp + (size_t)r * NH + bcol);
        }
    }
    __syncthreads();

    const int KT = NC / BK;  // 128
    for (int t = 0; t < KT; t++) {
        int cur = t & 1;
        float4 av0, av1, bv0, bv1;
        if (t + 1 < KT) {
            int k0 = (t + 1) * BK;
            const float* Xp = X + (size_t)m0 * NC + k0;
            av0 = *(const float4*)(Xp + (size_t)arow * NC + acol);
            av1 = *(const float4*)(Xp + (size_t)(arow + 64) * NC + acol);
            const float* Wp = W + (size_t)k0 * NH + n0;
            bv0 = *(const float4*)(Wp + (size_t)brow * NH + bcol);
            bv1 = *(const float4*)(Wp + (size_t)(brow + 8) * NH + bcol);
        }
#pragma unroll
        for (int k = 0; k < BK; k++) {
            float a[8], bb[8];
            *(float4*)&a[0] = *(const float4*)&As[cur][k][ty * 8];
            *(float4*)&a[4] = *(const float4*)&As[cur][k][ty * 8 + 4];
            *(float4*)&bb[0] = *(const float4*)&Bs[cur][k][tx * 8];
            *(float4*)&bb[4] = *(const float4*)&Bs[cur][k][tx * 8 + 4];
#pragma unroll
            for (int i = 0; i < 8; i++)
#pragma unroll
                for (int j = 0; j < 8; j++)
                    acc[i][j] = fmaf(a[i], bb[j], acc[i][j]);
        }
        if (t + 1 < KT) {
            int nxt = cur ^ 1;
            As[nxt][acol + 0][arow] = av0.x; As[nxt][acol + 1][arow] = av0.y;
            As[nxt][acol + 2][arow] = av0.z; As[nxt][acol + 3][arow] = av0.w;
            As[nxt][acol + 0][arow + 64] = av1.x; As[nxt][acol + 1][arow + 64] = av1.y;
            As[nxt][acol + 2][arow + 64] = av1.z; As[nxt][acol + 3][arow + 64] = av1.w;
            *(float4*)&Bs[nxt][brow][bcol] = bv0;
            *(float4*)&Bs[nxt][brow + 8][bcol] = bv1;
        }
        __syncthreads();
    }

    float* Op = Out + (size_t)(m0 + ty * 8) * NH + n0 + tx * 8;
#pragma unroll
    for (int i = 0; i < 8; i++) {
        *(float4*)(Op + (size_t)i * NH) =
            make_float4(acc[i][0], acc[i][1], acc[i][2], acc[i][3]);
        *(float4*)(Op + (size_t)i * NH + 4) =
            make_float4(acc[i][4], acc[i][5], acc[i][6], acc[i][7]);
    }
}

// ---------------------------------------------------------------------------
// Kernel 2: logits (transposed)  L[b][j][i] = sqrt(C) * Q[b][j] . K[b][i]
// Only upper blocks (bi >= bj). Masked entries (i<j, diag blocks) -> -INF.
// ---------------------------------------------------------------------------
__global__ void __launch_bounds__(256) logits_kernel()
{
    const int BK = 16;
    const int bi = blockIdx.x, bj = blockIdx.y, b = blockIdx.z;
    if (bi < bj) return;
    const int j0 = bj * 128;  // M dim (rows of L)
    const int i0 = bi * 128;  // N dim (cols of L)
    const float* Qb = g_Q + (size_t)b * NT * NH;
    const float* Kb = g_K + (size_t)b * NT * NH;

    __shared__ float As[2][BK][128];   // As[h][j]
    __shared__ float Bs[2][BK][128];   // Bs[h][i]

    const int tid = threadIdx.x;
    const int arow = tid >> 2;
    const int acol = (tid & 3) << 2;
    const int tx = tid & 15, ty = tid >> 4;

    float acc[8][8];
#pragma unroll
    for (int i = 0; i < 8; i++)
#pragma unroll
        for (int j = 0; j < 8; j++) acc[i][j] = 0.f;

    // prologue
    {
#pragma unroll
        for (int it = 0; it < 2; it++) {
            int r = arow + it * 64;
            float4 v = *(const float4*)(Qb + (size_t)(j0 + r) * NH + acol);
            As[0][acol + 0][r] = v.x; As[0][acol + 1][r] = v.y;
            As[0][acol + 2][r] = v.z; As[0][acol + 3][r] = v.w;
            float4 w = *(const float4*)(Kb + (size_t)(i0 + r) * NH + acol);
            Bs[0][acol + 0][r] = w.x; Bs[0][acol + 1][r] = w.y;
            Bs[0][acol + 2][r] = w.z; Bs[0][acol + 3][r] = w.w;
        }
    }
    __syncthreads();

    const int KT = NH / BK;  // 16
    for (int t = 0; t < KT; t++) {
        int cur = t & 1;
        float4 av0, av1, bv0, bv1;
        if (t + 1 < KT) {
            int k0 = (t + 1) * BK;
            av0 = *(const float4*)(Qb + (size_t)(j0 + arow) * NH + k0 + acol);
            av1 = *(const float4*)(Qb + (size_t)(j0 + arow + 64) * NH + k0 + acol);
            bv0 = *(const float4*)(Kb + (size_t)(i0 + arow) * NH + k0 + acol);
            bv1 = *(const float4*)(Kb + (size_t)(i0 + arow + 64) * NH + k0 + acol);
        }
#pragma unroll
        for (int k = 0; k < BK; k++) {
            float a[8], bb[8];
            *(float4*)&a[0] = *(const float4*)&As[cur][k][ty * 8];
            *(float4*)&a[4] = *(const float4*)&As[cur][k][ty * 8 + 4];
            *(float4*)&bb[0] = *(const float4*)&Bs[cur][k][tx * 8];
            *(float4*)&bb[4] = *(const float4*)&Bs[cur][k][tx * 8 + 4];
#pragma unroll
            for (int i = 0; i < 8; i++)
#pragma unroll
                for (int j = 0; j < 8; j++)
                    acc[i][j] = fmaf(a[i], bb[j], acc[i][j]);
        }
        if (t + 1 < KT) {
            int nxt = cur ^ 1;
            As[nxt][acol + 0][arow] = av0.x; As[nxt][acol + 1][arow] = av0.y;
            As[nxt][acol + 2][arow] = av0.z; As[nxt][acol + 3][arow] = av0.w;
            As[nxt][acol + 0][arow + 64] = av1.x; As[nxt][acol + 1][arow + 64] = av1.y;
            As[nxt][acol + 2][arow + 64] = av1.z; As[nxt][acol + 3][arow + 64] = av1.w;
            Bs[nxt][acol + 0][arow] = bv0.x; Bs[nxt][acol + 1][arow] = bv0.y;
            Bs[nxt][acol + 2][arow] = bv0.z; Bs[nxt][acol + 3][arow] = bv0.w;
            Bs[nxt][acol + 0][arow + 64] = bv1.x; Bs[nxt][acol + 1][arow + 64] = bv1.y;
            Bs[nxt][acol + 2][arow + 64] = bv1.z; Bs[nxt][acol + 3][arow + 64] = bv1.w;
        }
        __syncthreads();
    }

    const float scale = 45.25483399593904f;  // sqrt(2048)
    float* Lb = g_L + (size_t)b * NT * NT;
#pragma unroll
    for (int r = 0; r < 8; r++) {
        int jg = j0 + ty * 8 + r;
        int ib = i0 + tx * 8;
        float4 v0, v1;
        v0.x = (ib + 0 >= jg) ? acc[r][0] * scale : -INFINITY;
        v0.y = (ib + 1 >= jg) ? acc[r][1] * scale : -INFINITY;
        v0.z = (ib + 2 >= jg) ? acc[r][2] * scale : -INFINITY;
        v0.w = (ib + 3 >= jg) ? acc[r][3] * scale : -INFINITY;
        v1.x = (ib + 4 >= jg) ? acc[r][4] * scale : -INFINITY;
        v1.y = (ib + 5 >= jg) ? acc[r][5] * scale : -INFINITY;
        v1.z = (ib + 6 >= jg) ? acc[r][6] * scale : -INFINITY;
        v1.w = (ib + 7 >= jg) ? acc[r][7] * scale : -INFINITY;
        *(float4*)(Lb + (size_t)jg * NT + ib) = v0;
        *(float4*)(Lb + (size_t)jg * NT + ib + 4) = v1;
    }
}

// ---------------------------------------------------------------------------
// Kernel 3: per-column softmax stats (rows of L): m_j, 1/sum_j
// ---------------------------------------------------------------------------
__global__ void __launch_bounds__(128) stats_kernel()
{
    const int j = blockIdx.x, b = blockIdx.y;
    const float* row = g_L + (size_t)b * NT * NT + (size_t)j * NT;
    const int tid = threadIdx.x;

    float mx = -INFINITY;
    for (int i = j + tid; i < NT; i += 128) mx = fmaxf(mx, row[i]);
#pragma unroll
    for (int o = 16; o > 0; o >>= 1) mx = fmaxf(mx, __shfl_xor_sync(0xffffffffu, mx, o));

    __shared__ float redm[4];
    __shared__ float reds[4];
    const int w = tid >> 5, lane = tid & 31;
    if (lane == 0) redm[w] = mx;
    __syncthreads();
    mx = fmaxf(fmaxf(redm[0], redm[1]), fmaxf(redm[2], redm[3]));

    float s = 0.f;
    for (int i = j + tid; i < NT; i += 128) s += __expf(row[i] - mx);
#pragma unroll
    for (int o = 16; o > 0; o >>= 1) s += __shfl_xor_sync(0xffffffffu, s, o);
    if (lane == 0) reds[w] = s;
    __syncthreads();
    if (tid == 0) {
        s = reds[0] + reds[1] + reds[2] + reds[3];
        g_m[b * NT + j] = mx;
        g_rs[b * NT + j] = 1.0f / s;
    }
}

// ---------------------------------------------------------------------------
// Kernel 4: out[b][i][h] = sum_{j<=i} exp(L[j][i]-m_j)/s_j * V[b][j][h]
// P tile loads are already in [k=j][m=i] layout -> no transpose.
// Triangular K-loop: j tiles up to i0+128.
// ---------------------------------------------------------------------------
__global__ void __launch_bounds__(256) av_kernel(float* __restrict__ Out)
{
    const int BK = 16;
    const int b = blockIdx.z;
    const int i0 = blockIdx.y * 128;
    const int h0 = blockIdx.x * 128;
    const float* Lb = g_L + (size_t)b * NT * NT;
    const float* Vb = g_V + (size_t)b * NT * NH;
    const float* mb = g_m + b * NT;
    const float* rb = g_rs + b * NT;

    __shared__ float Ps[2][BK][128];   // Ps[j][i]
    __shared__ float Vs[2][BK][128];   // Vs[j][h]

    const int tid = threadIdx.x;
    const int prow = tid >> 5;          // 0..7 (+8)
    const int pcol = (tid & 31) << 2;   // 0..124
    const int tx = tid & 15, ty = tid >> 4;

    float acc[8][8];
#pragma unroll
    for (int i = 0; i < 8; i++)
#pragma unroll
        for (int j = 0; j < 8; j++) acc[i][j] = 0.f;

    const int KT = (i0 + 128) / BK;  // j < i0+128 suffices (j<=i)

    // prologue: tile 0
    {
#pragma unroll
        for (int it = 0; it < 2; it++) {
            int jg = prow + it * 8;
            float4 lv = *(const float4*)(Lb + (size_t)jg * NT + i0 + pcol);
            float mj = mb[jg], rj = rb[jg];
            float4 p;
            p.x = __expf(lv.x - mj) * rj;
            p.y = __expf(lv.y - mj) * rj;
            p.z = __expf(lv.z - mj) * rj;
            p.w = __expf(lv.w - mj) * rj;
            *(float4*)&Ps[0][prow + it * 8][pcol] = p;
            *(float4*)&Vs[0][prow + it * 8][pcol] =
                *(const float4*)(Vb + (size_t)jg * NH + h0 + pcol);
        }
    }
    __syncthreads();

    for (int t = 0; t < KT; t++) {
        int cur = t & 1;
        float4 pv0, pv1, vv0, vv1;
        if (t + 1 < KT) {
            int j0 = (t + 1) * BK;
            int jg0 = j0 + prow, jg1 = j0 + prow + 8;
            float4 l0 = *(const float4*)(Lb + (size_t)jg0 * NT + i0 + pcol);
            float4 l1 = *(const float4*)(Lb + (size_t)jg1 * NT + i0 + pcol);
            float m0 = mb[jg0], r0 = rb[jg0];
            float m1 = mb[jg1], r1 = rb[jg1];
            pv0.x = __expf(l0.x - m0) * r0; pv0.y = __expf(l0.y - m0) * r0;
            pv0.z = __expf(l0.z - m0) * r0; pv0.w = __expf(l0.w - m0) * r0;
            pv1.x = __expf(l1.x - m1) * r1; pv1.y = __expf(l1.y - m1) * r1;
            pv1.z = __expf(l1.z - m1) * r1; pv1.w = __expf(l1.w - m1) * r1;
            vv0 = *(const float4*)(Vb + (size_t)jg0 * NH + h0 + pcol);
            vv1 = *(const float4*)(Vb + (size_t)jg1 * NH + h0 + pcol);
        }
#pragma unroll
        for (int k = 0; k < BK; k++) {
            float a[8], bb[8];
            *(float4*)&a[0] = *(const float4*)&Ps[cur][k][ty * 8];
            *(float4*)&a[4] = *(const float4*)&Ps[cur][k][ty * 8 + 4];
            *(float4*)&bb[0] = *(const float4*)&Vs[cur][k][tx * 8];
            *(float4*)&bb[4] = *(const float4*)&Vs[cur][k][tx * 8 + 4];
#pragma unroll
            for (int i = 0; i < 8; i++)
#pragma unroll
                for (int j = 0; j < 8; j++)
                    acc[i][j] = fmaf(a[i], bb[j], acc[i][j]);
        }
        if (t + 1 < KT) {
            int nxt = cur ^ 1;
            *(float4*)&Ps[nxt][prow][pcol] = pv0;
            *(float4*)&Ps[nxt][prow + 8][pcol] = pv1;
            *(float4*)&Vs[nxt][prow][pcol] = vv0;
            *(float4*)&Vs[nxt][prow + 8][pcol] = vv1;
        }
        __syncthreads();
    }

    float* Op = Out + (size_t)(b * NT + i0 + ty * 8) * NH + h0 + tx * 8;
#pragma unroll
    for (int i = 0; i < 8; i++) {
        *(float4*)(Op + (size_t)i * NH) =
            make_float4(acc[i][0], acc[i][1], acc[i][2], acc[i][3]);
        *(float4*)(Op + (size_t)i * NH + 4) =
            make_float4(acc[i][4], acc[i][5], acc[i][6], acc[i][7]);
    }
}

// ---------------------------------------------------------------------------
extern "C" void kernel_launch(void* const* d_in, const int* in_sizes, int n_in,
                              void* d_out, int out_size)
{
    const float* X  = (const float*)d_in[0];   // token_embd [16,2048,2048]
    const float* Wk = (const float*)d_in[1];   // [2048,256]
    const float* Wq = (const float*)d_in[2];
    const float* Wv = (const float*)d_in[3];
    float* out = (float*)d_out;                // [16,2048,256] fp32

    dim3 gp(NH / 128, BTOT / 128);             // (2, 256)
    proj_kernel<<<gp, 256>>>(X, Wk, 0);
    proj_kernel<<<gp, 256>>>(X, Wq, 1);
    proj_kernel<<<gp, 256>>>(X, Wv, 2);

    dim3 gl(NT / 128, NT / 128, NB);           // (16,16,16)
    logits_kernel<<<gl, 256>>>();

    dim3 gs(NT, NB);                           // (2048,16)
    stats_kernel<<<gs, 128>>>();

    dim3 ga(NH / 128, NT / 128, NB);           // (2,16,16)
    av_kernel<<<ga, 256>>>(out);
}

// round 5
// speedup vs baseline: 1.4939x; 1.4939x over previous
#include <cuda_runtime.h>
#include <cuda_bf16.h>
#include <math.h>
#include <stdint.h>

#define NB 16
#define NT 2048
#define NC 2048
#define NH 256
#define BTOT (NB * NT)   // 32768 rows

// Scratch (device globals: allocation-free per harness rules)
__device__ float g_K[BTOT * NH];
__device__ float g_Q[BTOT * NH];
__device__ float g_V[BTOT * NH];
__device__ float g_L[NB * NT * NT];         // 268 MB, L[b][j][i]
__device__ float g_m[BTOT];
__device__ float g_rs[BTOT];
// Pre-split transposed weights: [which][term][n=256][k=2048] bf16
__device__ __nv_bfloat16 g_Wt[3][3 * 256 * 2048];

// ---------------------------------------------------------------------------
__device__ __forceinline__ uint32_t smem_u32(const void* p) {
    uint32_t a;
    asm("{ .reg .u64 t; cvta.to.shared.u64 t, %1; cvt.u32.u64 %0, t; }"
        : "=r"(a) : "l"(p));
    return a;
}
__device__ __forceinline__ uint32_t sw64(uint32_t o) { return o ^ ((o >> 3) & 0x30); }

__device__ __forceinline__ void ldsm_x4(uint32_t& r0, uint32_t& r1, uint32_t& r2,
                                        uint32_t& r3, uint32_t addr) {
    asm volatile("ldmatrix.sync.aligned.m8n8.x4.shared.b16 {%0,%1,%2,%3}, [%4];"
                 : "=r"(r0), "=r"(r1), "=r"(r2), "=r"(r3) : "r"(addr));
}
__device__ __forceinline__ void mma_bf16(float* d, uint32_t a0, uint32_t a1,
                                         uint32_t a2, uint32_t a3,
                                         uint32_t b0, uint32_t b1) {
    asm volatile(
        "mma.sync.aligned.m16n8k16.row.col.f32.bf16.bf16.f32 "
        "{%0,%1,%2,%3}, {%4,%5,%6,%7}, {%8,%9}, {%0,%1,%2,%3};"
        : "+f"(d[0]), "+f"(d[1]), "+f"(d[2]), "+f"(d[3])
        : "r"(a0), "r"(a1), "r"(a2), "r"(a3), "r"(b0), "r"(b1));
}
__device__ __forceinline__ void cp_async16(uint32_t dst, const void* src) {
    asm volatile("cp.async.cg.shared.global [%0], [%1], 16;"
                 :: "r"(dst), "l"(src) : "memory");
}
#define CP_COMMIT() asm volatile("cp.async.commit_group;" ::: "memory")
#define CP_WAIT0()  asm volatile("cp.async.wait_group 0;" ::: "memory")

__device__ __forceinline__ void split3u(float x, uint16_t& u1, uint16_t& u2, uint16_t& u3) {
    __nv_bfloat16 b1 = __float2bfloat16_rn(x);
    float f1 = __bfloat162float(b1);
    float r = x - f1;
    __nv_bfloat16 b2 = __float2bfloat16_rn(r);
    float f2 = __bfloat162float(b2);
    __nv_bfloat16 b3 = __float2bfloat16_rn(r - f2);
    u1 = __bfloat16_as_ushort(b1);
    u2 = __bfloat16_as_ushort(b2);
    u3 = __bfloat16_as_ushort(b3);
}

// ---------------------------------------------------------------------------
// Kernel 0: pre-split + transpose weights: g_Wt[w][t][n][k] = term_t(W[k][n])
// ---------------------------------------------------------------------------
__global__ void wprep_kernel(const float* __restrict__ Wk,
                             const float* __restrict__ Wq,
                             const float* __restrict__ Wv)
{
    const float* W = (blockIdx.z == 0) ? Wk : (blockIdx.z == 1) ? Wq : Wv;
    __nv_bfloat16* dst = g_Wt[blockIdx.z];
    __shared__ float tile[32][33];
    int k0 = blockIdx.x * 32, n0 = blockIdx.y * 32;
    int tx = threadIdx.x, ty = threadIdx.y;  // (32, 8)
#pragma unroll
    for (int i = 0; i < 32; i += 8)
        tile[ty + i][tx] = W[(size_t)(k0 + ty + i) * NH + n0 + tx];
    __syncthreads();
#pragma unroll
    for (int i = 0; i < 32; i += 8) {
        int n = n0 + ty + i, k = k0 + tx;
        uint16_t u1, u2, u3;
        split3u(tile[tx][ty + i], u1, u2, u3);
        size_t o = (size_t)n * NC + k;
        dst[0 * (size_t)256 * 2048 + o] = __ushort_as_bfloat16(u1);
        dst[1 * (size_t)256 * 2048 + o] = __ushort_as_bfloat16(u2);
        dst[2 * (size_t)256 * 2048 + o] = __ushort_as_bfloat16(u3);
    }
}

// ---------------------------------------------------------------------------
// Kernel 1: mma.sync projection.  Out[M=BT][N=256] = X[M][K=2048] @ W[K][N]
// fp32 via bf16 split: NPROD=6 (K,Q: terms 11,12,21,13,31,22) or 3 (V).
// CTA: 256 thr, tile 128x256, K-chunk 32, double-buffered, cp.async weights.
// ---------------------------------------------------------------------------
#define CHUNK 32
#define NCHUNK (NC / CHUNK)      // 64
#define A_TILE 8192              // 128 rows x 64B
#define B_TILE 16384             // 256 rows x 64B
#define STAGE  (3 * A_TILE + 3 * B_TILE)   // 73728
#define PROJ_SMEM (2 * STAGE)              // 147456

__device__ __forceinline__ uint32_t a_off(int buf, int t) { return buf * STAGE + t * A_TILE; }
__device__ __forceinline__ uint32_t b_off(int buf, int t) { return buf * STAGE + 3 * A_TILE + t * B_TILE; }

template <int NPROD>
__global__ void __launch_bounds__(256, 1) proj_mma_kernel(const float* __restrict__ X)
{
    extern __shared__ char sm[];
    const uint32_t smb = smem_u32(sm);
    const int tid = threadIdx.x;
    const int wid = tid >> 5, lane = tid & 31;
    const int wr = wid >> 2, wc = wid & 3;       // warp grid 2x4 over (128,256)
    const int which = (NPROD == 6) ? blockIdx.y : 2;
    const int m0 = blockIdx.x * 128;
    const int NTERM = (NPROD == 6) ? 3 : 2;

    const __nv_bfloat16* Wt = g_Wt[which];

    // product term lists (A-term, B-term), 0-based
    const int TA0 = 0, TB0 = 0;
    const int TA1 = 0, TB1 = 1;
    const int TA2 = 1, TB2 = 0;
    const int TA3 = 0, TB3 = 2;
    const int TA4 = 2, TB4 = 0;
    const int TA5 = 1, TB5 = 1;

    float acc[4][8][4];
#pragma unroll
    for (int i = 0; i < 4; i++)
#pragma unroll
        for (int j = 0; j < 8; j++)
#pragma unroll
            for (int q = 0; q < 4; q++) acc[i][j][q] = 0.f;

    // per-thread loader coords
    const int ar = tid >> 3;            // 0..31 (x4 iters -> rows via +32)
    const int af = tid & 7;             // float4 within 32-fp32 row
    const int bn = tid >> 2;            // 0..63 (x4 iters -> n via +64)
    const int bu = tid & 3;             // 16B granule within 64B row

    // ---- helpers as lambdas ----
    auto load_x_regs = [&](int c, float4* xv) {
        const float* Xp = X + (size_t)m0 * NC + c * CHUNK;
#pragma unroll
        for (int it = 0; it < 4; it++) {
            int r = ar + it * 32;
            xv[it] = *(const float4*)(Xp + (size_t)r * NC + af * 4);
        }
    };
    auto store_a = [&](int buf, const float4* xv) {
#pragma unroll
        for (int it = 0; it < 4; it++) {
            int r = ar + it * 32;
            uint16_t x1, x2, x3, y1, y2, y3, z1, z2, z3, w1, w2, w3;
            split3u(xv[it].x, x1, x2, x3);
            split3u(xv[it].y, y1, y2, y3);
            split3u(xv[it].z, z1, z2, z3);
            split3u(xv[it].w, w1, w2, w3);
            uint32_t off = sw64((uint32_t)(r * 64 + af * 8));
            *(uint2*)(sm + a_off(buf, 0) + off) =
                make_uint2((uint32_t)x1 | ((uint32_t)y1 << 16), (uint32_t)z1 | ((uint32_t)w1 << 16));
            *(uint2*)(sm + a_off(buf, 1) + off) =
                make_uint2((uint32_t)x2 | ((uint32_t)y2 << 16), (uint32_t)z2 | ((uint32_t)w2 << 16));
            if (NPROD == 6)
                *(uint2*)(sm + a_off(buf, 2) + off) =
                    make_uint2((uint32_t)x3 | ((uint32_t)y3 << 16), (uint32_t)z3 | ((uint32_t)w3 << 16));
        }
    };
    auto issue_b = [&](int c, int buf) {
#pragma unroll
        for (int t = 0; t < 3; t++) {
            if (t >= NTERM) break;
            const __nv_bfloat16* src = Wt + (size_t)t * 256 * 2048 + c * CHUNK;
#pragma unroll
            for (int it = 0; it < 4; it++) {
                int n = bn + it * 64;
                cp_async16(smb + b_off(buf, t) + sw64((uint32_t)(n * 64 + bu * 16)),
                           src + (size_t)n * NC + bu * 8);
            }
        }
        CP_COMMIT();
    };

    auto mma_chunk = [&](int buf) {
#pragma unroll
        for (int ks = 0; ks < 2; ks++) {
            const int kb = ks * 32;
            const uint32_t a_row = (uint32_t)((wr * 64 + (lane & 15)) * 64 + kb + (lane >> 4) * 16);
            const uint32_t b_row = (uint32_t)((wc * 64 + (lane & 7) + ((lane >> 4) & 1) * 8) * 64 +
                                              kb + ((lane >> 3) & 1) * 16);
#pragma unroll
            for (int p = 0; p < NPROD; p++) {
                const int ta = (p == 0) ? TA0 : (p == 1) ? TA1 : (p == 2) ? TA2
                             : (p == 3) ? TA3 : (p == 4) ? TA4 : TA5;
                const int tb = (p == 0) ? TB0 : (p == 1) ? TB1 : (p == 2) ? TB2
                             : (p == 3) ? TB3 : (p == 4) ? TB4 : TB5;
                uint32_t af4[4][4];
                const uint32_t abase = smb + a_off(buf, ta);
#pragma unroll
                for (int mi = 0; mi < 4; mi++)
                    ldsm_x4(af4[mi][0], af4[mi][1], af4[mi][2], af4[mi][3],
                            abase + sw64(a_row + (uint32_t)(mi * 16 * 64)));
                const uint32_t bbase = smb + b_off(buf, tb);
#pragma unroll
                for (int nj = 0; nj < 4; nj++) {
                    uint32_t b4[4];
                    ldsm_x4(b4[0], b4[1], b4[2], b4[3],
                            bbase + sw64(b_row + (uint32_t)(nj * 16 * 64)));
#pragma unroll
                    for (int mi = 0; mi < 4; mi++) {
                        mma_bf16(acc[mi][2 * nj], af4[mi][0], af4[mi][1], af4[mi][2], af4[mi][3],
                                 b4[0], b4[1]);
                        mma_bf16(acc[mi][2 * nj + 1], af4[mi][0], af4[mi][1], af4[mi][2], af4[mi][3],
                                 b4[2], b4[3]);
                    }
                }
            }
        }
    };

    // ---- prologue: chunk 0 ----
    {
        float4 xv[4];
        load_x_regs(0, xv);
        issue_b(0, 0);
        store_a(0, xv);
        CP_WAIT0();
        __syncthreads();
    }

    // ---- main loop ----
    for (int c = 0; c < NCHUNK; c++) {
        const int cur = c & 1;
        float4 xv[4];
        if (c + 1 < NCHUNK) {
            load_x_regs(c + 1, xv);
            issue_b(c + 1, cur ^ 1);
        }
        mma_chunk(cur);
        if (c + 1 < NCHUNK) {
            store_a(cur ^ 1, xv);
            CP_WAIT0();
        }
        __syncthreads();
    }

    // ---- epilogue ----
    float* Out = (which == 0) ? g_K : (which == 1) ? g_Q : g_V;
#pragma unroll
    for (int mi = 0; mi < 4; mi++) {
        int m = m0 + wr * 64 + mi * 16 + (lane >> 2);
#pragma unroll
        for (int jj = 0; jj < 8; jj++) {
            int n = wc * 64 + jj * 8 + (lane & 3) * 2;
            *(float2*)(Out + (size_t)m * NH + n) = make_float2(acc[mi][jj][0], acc[mi][jj][1]);
            *(float2*)(Out + (size_t)(m + 8) * NH + n) = make_float2(acc[mi][jj][2], acc[mi][jj][3]);
        }
    }
}

// ---------------------------------------------------------------------------
// Kernel 2: logits (transposed)  L[b][j][i] = sqrt(C) * Q[b][j] . K[b][i]
// (fp32 SGEMM, unchanged from R3-passing version)
// ---------------------------------------------------------------------------
__global__ void __launch_bounds__(256) logits_kernel()
{
    const int BK = 16;
    const int bi = blockIdx.x, bj = blockIdx.y, b = blockIdx.z;
    if (bi < bj) return;
    const int j0 = bj * 128;
    const int i0 = bi * 128;
    const float* Qb = g_Q + (size_t)b * NT * NH;
    const float* Kb = g_K + (size_t)b * NT * NH;

    __shared__ float As[2][BK][128];
    __shared__ float Bs[2][BK][128];

    const int tid = threadIdx.x;
    const int arow = tid >> 2;
    const int acol = (tid & 3) << 2;
    const int tx = tid & 15, ty = tid >> 4;

    float acc[8][8];
#pragma unroll
    for (int i = 0; i < 8; i++)
#pragma unroll
        for (int j = 0; j < 8; j++) acc[i][j] = 0.f;

    {
#pragma unroll
        for (int it = 0; it < 2; it++) {
            int r = arow + it * 64;
            float4 v = *(const float4*)(Qb + (size_t)(j0 + r) * NH + acol);
            As[0][acol + 0][r] = v.x; As[0][acol + 1][r] = v.y;
            As[0][acol + 2][r] = v.z; As[0][acol + 3][r] = v.w;
            float4 w = *(const float4*)(Kb + (size_t)(i0 + r) * NH + acol);
            Bs[0][acol + 0][r] = w.x; Bs[0][acol + 1][r] = w.y;
            Bs[0][acol + 2][r] = w.z; Bs[0][acol + 3][r] = w.w;
        }
    }
    __syncthreads();

    const int KT = NH / BK;
    for (int t = 0; t < KT; t++) {
        int cur = t & 1;
        float4 av0, av1, bv0, bv1;
        if (t + 1 < KT) {
            int k0 = (t + 1) * BK;
            av0 = *(const float4*)(Qb + (size_t)(j0 + arow) * NH + k0 + acol);
            av1 = *(const float4*)(Qb + (size_t)(j0 + arow + 64) * NH + k0 + acol);
            bv0 = *(const float4*)(Kb + (size_t)(i0 + arow) * NH + k0 + acol);
            bv1 = *(const float4*)(Kb + (size_t)(i0 + arow + 64) * NH + k0 + acol);
        }
#pragma unroll
        for (int k = 0; k < BK; k++) {
            float a[8], bb[8];
            *(float4*)&a[0] = *(const float4*)&As[cur][k][ty * 8];
            *(float4*)&a[4] = *(const float4*)&As[cur][k][ty * 8 + 4];
            *(float4*)&bb[0] = *(const float4*)&Bs[cur][k][tx * 8];
            *(float4*)&bb[4] = *(const float4*)&Bs[cur][k][tx * 8 + 4];
#pragma unroll
            for (int i = 0; i < 8; i++)
#pragma unroll
                for (int j = 0; j < 8; j++)
                    acc[i][j] = fmaf(a[i], bb[j], acc[i][j]);
        }
        if (t + 1 < KT) {
            int nxt = cur ^ 1;
            As[nxt][acol + 0][arow] = av0.x; As[nxt][acol + 1][arow] = av0.y;
            As[nxt][acol + 2][arow] = av0.z; As[nxt][acol + 3][arow] = av0.w;
            As[nxt][acol + 0][arow + 64] = av1.x; As[nxt][acol + 1][arow + 64] = av1.y;
            As[nxt][acol + 2][arow + 64] = av1.z; As[nxt][acol + 3][arow + 64] = av1.w;
            Bs[nxt][acol + 0][arow] = bv0.x; Bs[nxt][acol + 1][arow] = bv0.y;
            Bs[nxt][acol + 2][arow] = bv0.z; Bs[nxt][acol + 3][arow] = bv0.w;
            Bs[nxt][acol + 0][arow + 64] = bv1.x; Bs[nxt][acol + 1][arow + 64] = bv1.y;
            Bs[nxt][acol + 2][arow + 64] = bv1.z; Bs[nxt][acol + 3][arow + 64] = bv1.w;
        }
        __syncthreads();
    }

    const float scale = 45.25483399593904f;  // sqrt(2048)
    float* Lb = g_L + (size_t)b * NT * NT;
#pragma unroll
    for (int r = 0; r < 8; r++) {
        int jg = j0 + ty * 8 + r;
        int ib = i0 + tx * 8;
        float4 v0, v1;
        v0.x = (ib + 0 >= jg) ? acc[r][0] * scale : -INFINITY;
        v0.y = (ib + 1 >= jg) ? acc[r][1] * scale : -INFINITY;
        v0.z = (ib + 2 >= jg) ? acc[r][2] * scale : -INFINITY;
        v0.w = (ib + 3 >= jg) ? acc[r][3] * scale : -INFINITY;
        v1.x = (ib + 4 >= jg) ? acc[r][4] * scale : -INFINITY;
        v1.y = (ib + 5 >= jg) ? acc[r][5] * scale : -INFINITY;
        v1.z = (ib + 6 >= jg) ? acc[r][6] * scale : -INFINITY;
        v1.w = (ib + 7 >= jg) ? acc[r][7] * scale : -INFINITY;
        *(float4*)(Lb + (size_t)jg * NT + ib) = v0;
        *(float4*)(Lb + (size_t)jg * NT + ib + 4) = v1;
    }
}

// ---------------------------------------------------------------------------
// Kernel 3: per-column softmax stats (rows of L): m_j, 1/sum_j
// ---------------------------------------------------------------------------
__global__ void __launch_bounds__(128) stats_kernel()
{
    const int j = blockIdx.x, b = blockIdx.y;
    const float* row = g_L + (size_t)b * NT * NT + (size_t)j * NT;
    const int tid = threadIdx.x;

    float mx = -INFINITY;
    for (int i = j + tid; i < NT; i += 128) mx = fmaxf(mx, row[i]);
#pragma unroll
    for (int o = 16; o > 0; o >>= 1) mx = fmaxf(mx, __shfl_xor_sync(0xffffffffu, mx, o));

    __shared__ float redm[4];
    __shared__ float reds[4];
    const int w = tid >> 5, lane = tid & 31;
    if (lane == 0) redm[w] = mx;
    __syncthreads();
    mx = fmaxf(fmaxf(redm[0], redm[1]), fmaxf(redm[2], redm[3]));

    float s = 0.f;
    for (int i = j + tid; i < NT; i += 128) s += __expf(row[i] - mx);
#pragma unroll
    for (int o = 16; o > 0; o >>= 1) s += __shfl_xor_sync(0xffffffffu, s, o);
    if (lane == 0) reds[w] = s;
    __syncthreads();
    if (tid == 0) {
        s = reds[0] + reds[1] + reds[2] + reds[3];
        g_m[b * NT + j] = mx;
        g_rs[b * NT + j] = 1.0f / s;
    }
}

// ---------------------------------------------------------------------------
// Kernel 4: out[b][i][h] = sum_{j<=i} exp(L[j][i]-m_j)/s_j * V[b][j][h]
// ---------------------------------------------------------------------------
__global__ void __launch_bounds__(256) av_kernel(float* __restrict__ Out)
{
    const int BK = 16;
    const int b = blockIdx.z;
    const int i0 = blockIdx.y * 128;
    const int h0 = blockIdx.x * 128;
    const float* Lb = g_L + (size_t)b * NT * NT;
    const float* Vb = g_V + (size_t)b * NT * NH;
    const float* mb = g_m + b * NT;
    const float* rb = g_rs + b * NT;

    __shared__ float Ps[2][BK][128];
    __shared__ float Vs[2][BK][128];

    const int tid = threadIdx.x;
    const int prow = tid >> 5;
    const int pcol = (tid & 31) << 2;
    const int tx = tid & 15, ty = tid >> 4;

    float acc[8][8];
#pragma unroll
    for (int i = 0; i < 8; i++)
#pragma unroll
        for (int j = 0; j < 8; j++) acc[i][j] = 0.f;

    const int KT = (i0 + 128) / BK;

    {
#pragma unroll
        for (int it = 0; it < 2; it++) {
            int jg = prow + it * 8;
            float4 lv = *(const float4*)(Lb + (size_t)jg * NT + i0 + pcol);
            float mj = mb[jg], rj = rb[jg];
            float4 p;
            p.x = __expf(lv.x - mj) * rj;
            p.y = __expf(lv.y - mj) * rj;
            p.z = __expf(lv.z - mj) * rj;
            p.w = __expf(lv.w - mj) * rj;
            *(float4*)&Ps[0][prow + it * 8][pcol] = p;
            *(float4*)&Vs[0][prow + it * 8][pcol] =
                *(const float4*)(Vb + (size_t)jg * NH + h0 + pcol);
        }
    }
    __syncthreads();

    for (int t = 0; t < KT; t++) {
        int cur = t & 1;
        float4 pv0, pv1, vv0, vv1;
        if (t + 1 < KT) {
            int j0 = (t + 1) * BK;
            int jg0 = j0 + prow, jg1 = j0 + prow + 8;
            float4 l0 = *(const float4*)(Lb + (size_t)jg0 * NT + i0 + pcol);
            float4 l1 = *(const float4*)(Lb + (size_t)jg1 * NT + i0 + pcol);
            float m0 = mb[jg0], r0 = rb[jg0];
            float m1 = mb[jg1], r1 = rb[jg1];
            pv0.x = __expf(l0.x - m0) * r0; pv0.y = __expf(l0.y - m0) * r0;
            pv0.z = __expf(l0.z - m0) * r0; pv0.w = __expf(l0.w - m0) * r0;
            pv1.x = __expf(l1.x - m1) * r1; pv1.y = __expf(l1.y - m1) * r1;
            pv1.z = __expf(l1.z - m1) * r1; pv1.w = __expf(l1.w - m1) * r1;
            vv0 = *(const float4*)(Vb + (size_t)jg0 * NH + h0 + pcol);
            vv1 = *(const float4*)(Vb + (size_t)jg1 * NH + h0 + pcol);
        }
#pragma unroll
        for (int k = 0; k < BK; k++) {
            float a[8], bb[8];
            *(float4*)&a[0] = *(const float4*)&Ps[cur][k][ty * 8];
            *(float4*)&a[4] = *(const float4*)&Ps[cur][k][ty * 8 + 4];
            *(float4*)&bb[0] = *(const float4*)&Vs[cur][k][tx * 8];
            *(float4*)&bb[4] = *(const float4*)&Vs[cur][k][tx * 8 + 4];
#pragma unroll
            for (int i = 0; i < 8; i++)
#pragma unroll
                for (int j = 0; j < 8; j++)
                    acc[i][j] = fmaf(a[i], bb[j], acc[i][j]);
        }
        if (t + 1 < KT) {
            int nxt = cur ^ 1;
            *(float4*)&Ps[nxt][prow][pcol] = pv0;
            *(float4*)&Ps[nxt][prow + 8][pcol] = pv1;
            *(float4*)&Vs[nxt][prow][pcol] = vv0;
            *(float4*)&Vs[nxt][prow + 8][pcol] = vv1;
        }
        __syncthreads();
    }

    float* Op = Out + (size_t)(b * NT + i0 + ty * 8) * NH + h0 + tx * 8;
#pragma unroll
    for (int i = 0; i < 8; i++) {
        *(float4*)(Op + (size_t)i * NH) =
            make_float4(acc[i][0], acc[i][1], acc[i][2], acc[i][3]);
        *(float4*)(Op + (size_t)i * NH + 4) =
            make_float4(acc[i][4], acc[i][5], acc[i][6], acc[i][7]);
    }
}

// ---------------------------------------------------------------------------
extern "C" void kernel_launch(void* const* d_in, const int* in_sizes, int n_in,
                              void* d_out, int out_size)
{
    const float* X  = (const float*)d_in[0];   // token_embd [16,2048,2048]
    const float* Wk = (const float*)d_in[1];   // [2048,256]
    const float* Wq = (const float*)d_in[2];
    const float* Wv = (const float*)d_in[3];
    float* out = (float*)d_out;                // [16,2048,256] fp32

    cudaFuncSetAttribute(proj_mma_kernel<6>,
                         cudaFuncAttributeMaxDynamicSharedMemorySize, PROJ_SMEM);
    cudaFuncSetAttribute(proj_mma_kernel<3>,
                         cudaFuncAttributeMaxDynamicSharedMemorySize, PROJ_SMEM);

    dim3 gw(NC / 32, NH / 32, 3);              // (64, 8, 3)
    wprep_kernel<<<gw, dim3(32, 8)>>>(Wk, Wq, Wv);

    proj_mma_kernel<6><<<dim3(BTOT / 128, 2), 256, PROJ_SMEM>>>(X);  // K, Q
    proj_mma_kernel<3><<<dim3(BTOT / 128, 1), 256, PROJ_SMEM>>>(X);  // V

    dim3 gl(NT / 128, NT / 128, NB);           // (16,16,16)
    logits_kernel<<<gl, 256>>>();

    dim3 gs(NT, NB);                           // (2048,16)
    stats_kernel<<<gs, 128>>>();

    dim3 ga(NH / 128, NT / 128, NB);           // (2,16,16)
    av_kernel<<<ga, 256>>>(out);
}

// round 7
// speedup vs baseline: 2.1383x; 1.4313x over previous
#include <cuda_runtime.h>
#include <cuda_fp16.h>
#include <math.h>
#include <stdint.h>

#define NB 16
#define NT 2048
#define NC 2048
#define NH 256
#define BTOT (NB * NT)   // 32768 rows

// Scratch (device globals: allocation-free per harness rules)
__device__ float g_V[BTOT * NH];
__device__ float g_L[NB * NT * NT];         // 268 MB, L[b][j][i]
__device__ float g_m[BTOT];
__device__ float g_rs[BTOT];
__device__ __half g_Xh[2][(size_t)BTOT * NC];   // X fp16 2-term split (268 MB)
__device__ __half g_Wt[3][2 * NH * NC];         // W*64 transposed, 2-term split
__device__ __half g_Kh[2][BTOT * NH];           // K fp16 2-term split
__device__ __half g_Qh[2][BTOT * NH];           // Q fp16 2-term split

// ---------------------------------------------------------------------------
__device__ __forceinline__ uint32_t smem_u32(const void* p) {
    uint32_t a;
    asm("{ .reg .u64 t; cvta.to.shared.u64 t, %1; cvt.u32.u64 %0, t; }"
        : "=r"(a) : "l"(p));
    return a;
}
__device__ __forceinline__ uint32_t sw64(uint32_t o) { return o ^ ((o >> 3) & 0x30); }

__device__ __forceinline__ void ldsm_x4(uint32_t& r0, uint32_t& r1, uint32_t& r2,
                                        uint32_t& r3, uint32_t addr) {
    asm volatile("ldmatrix.sync.aligned.m8n8.x4.shared.b16 {%0,%1,%2,%3}, [%4];"
                 : "=r"(r0), "=r"(r1), "=r"(r2), "=r"(r3) : "r"(addr));
}
__device__ __forceinline__ void mma_h(float* d, uint32_t a0, uint32_t a1,
                                      uint32_t a2, uint32_t a3,
                                      uint32_t b0, uint32_t b1) {
    asm volatile(
        "mma.sync.aligned.m16n8k16.row.col.f32.f16.f16.f32 "
        "{%0,%1,%2,%3}, {%4,%5,%6,%7}, {%8,%9}, {%0,%1,%2,%3};"
        : "+f"(d[0]), "+f"(d[1]), "+f"(d[2]), "+f"(d[3])
        : "r"(a0), "r"(a1), "r"(a2), "r"(a3), "r"(b0), "r"(b1));
}
__device__ __forceinline__ void cp_async16(uint32_t dst, const void* src) {
    asm volatile("cp.async.cg.shared.global [%0], [%1], 16;"
                 :: "r"(dst), "l"(src) : "memory");
}
#define CP_COMMIT() asm volatile("cp.async.commit_group;" ::: "memory")
#define CP_WAIT0()  asm volatile("cp.async.wait_group 0;" ::: "memory")

// SMEM layout shared by proj & logits GEMM cores:
// A: 2 terms x 128 rows x 64B, B: 2 terms x 256 rows x 64B, double buffered.
#define A_T 8192
#define B_T 16384
#define STG (2 * A_T + 2 * B_T)     // 49152
#define GEMM_SMEM (2 * STG)         // 98304
__device__ __forceinline__ uint32_t a_off(int buf, int t) { return buf * STG + t * A_T; }
__device__ __forceinline__ uint32_t b_off(int buf, int t) { return buf * STG + 2 * A_T + t * B_T; }

// 3-product fp16 split MMA over one 32-wide K chunk (terms: a1b1, a1b2, a2b1)
__device__ __forceinline__ void mma_chunk3(uint32_t smb, int buf, int wr, int wc,
                                           int lane, float (*acc)[8][4]) {
    const int TA[3] = {0, 0, 1};
    const int TB[3] = {0, 1, 0};
#pragma unroll
    for (int ks = 0; ks < 2; ks++) {
        const uint32_t kb = ks * 32;
        const uint32_t a_row = (uint32_t)((wr * 64 + (lane & 15)) * 64) + kb + (lane >> 4) * 16;
        const uint32_t b_row = (uint32_t)((wc * 64 + (lane & 7) + ((lane >> 4) & 1) * 8) * 64) +
                               kb + ((lane >> 3) & 1) * 16;
#pragma unroll
        for (int p = 0; p < 3; p++) {
            const uint32_t abase = smb + a_off(buf, TA[p]);
            uint32_t af4[4][4];
#pragma unroll
            for (int mi = 0; mi < 4; mi++)
                ldsm_x4(af4[mi][0], af4[mi][1], af4[mi][2], af4[mi][3],
                        abase + sw64(a_row + (uint32_t)(mi * 16 * 64)));
            const uint32_t bbase = smb + b_off(buf, TB[p]);
#pragma unroll
            for (int nj = 0; nj < 4; nj++) {
                uint32_t b4[4];
                ldsm_x4(b4[0], b4[1], b4[2], b4[3],
                        bbase + sw64(b_row + (uint32_t)(nj * 16 * 64)));
#pragma unroll
                for (int mi = 0; mi < 4; mi++) {
                    mma_h(acc[mi][2 * nj], af4[mi][0], af4[mi][1], af4[mi][2], af4[mi][3],
                          b4[0], b4[1]);
                    mma_h(acc[mi][2 * nj + 1], af4[mi][0], af4[mi][1], af4[mi][2], af4[mi][3],
                          b4[2], b4[3]);
                }
            }
        }
    }
}

// ---------------------------------------------------------------------------
// Kernel 0a: split X once into fp16 2-term globals
// ---------------------------------------------------------------------------
__global__ void xsplit_kernel(const float* __restrict__ X)
{
    const size_t n4 = (size_t)BTOT * NC / 4;
    const size_t stride = (size_t)gridDim.x * blockDim.x;
    uint2* o1 = (uint2*)g_Xh[0];
    uint2* o2 = (uint2*)g_Xh[1];
    for (size_t i = (size_t)blockIdx.x * blockDim.x + threadIdx.x; i < n4; i += stride) {
        float4 v = ((const float4*)X)[i];
        __half x1 = __float2half_rn(v.x), y1 = __float2half_rn(v.y);
        __half z1 = __float2half_rn(v.z), w1 = __float2half_rn(v.w);
        __half x2 = __float2half_rn(v.x - __half2float(x1));
        __half y2 = __float2half_rn(v.y - __half2float(y1));
        __half z2 = __float2half_rn(v.z - __half2float(z1));
        __half w2 = __float2half_rn(v.w - __half2float(w1));
        o1[i] = make_uint2((uint32_t)__half_as_ushort(x1) | ((uint32_t)__half_as_ushort(y1) << 16),
                           (uint32_t)__half_as_ushort(z1) | ((uint32_t)__half_as_ushort(w1) << 16));
        o2[i] = make_uint2((uint32_t)__half_as_ushort(x2) | ((uint32_t)__half_as_ushort(y2) << 16),
                           (uint32_t)__half_as_ushort(z2) | ((uint32_t)__half_as_ushort(w2) << 16));
    }
}

// ---------------------------------------------------------------------------
// Kernel 0b: weights: transpose, scale x64 (avoid fp16 subnormals), 2-term split
// g_Wt[w][t][n][k] = term_t(64 * W[k][n])
// ---------------------------------------------------------------------------
__global__ void wprep_kernel(const float* __restrict__ Wk,
                             const float* __restrict__ Wq,
                             const float* __restrict__ Wv)
{
    const float* W = (blockIdx.z == 0) ? Wk : (blockIdx.z == 1) ? Wq : Wv;
    __half* dst = g_Wt[blockIdx.z];
    __shared__ float tile[32][33];
    int k0 = blockIdx.x * 32, n0 = blockIdx.y * 32;
    int tx = threadIdx.x, ty = threadIdx.y;  // (32, 8)
#pragma unroll
    for (int i = 0; i < 32; i += 8)
        tile[ty + i][tx] = W[(size_t)(k0 + ty + i) * NH + n0 + tx];
    __syncthreads();
#pragma unroll
    for (int i = 0; i < 32; i += 8) {
        int n = n0 + ty + i, k = k0 + tx;
        float w = tile[tx][ty + i] * 64.0f;
        __half h1 = __float2half_rn(w);
        __half h2 = __float2half_rn(w - __half2float(h1));
        size_t o = (size_t)n * NC + k;
        dst[o] = h1;
        dst[(size_t)NH * NC + o] = h2;
    }
}

// ---------------------------------------------------------------------------
// Kernel 1: projection (fp16 split MMA).  which = blockIdx.y: 0=K 1=Q 2=V
// Tile 128x256, K=2048 in 32-chunks. K,Q epilogue -> fp16 split pairs; V -> fp32.
// ---------------------------------------------------------------------------
__global__ void __launch_bounds__(256, 1) proj_h_kernel()
{
    extern __shared__ char sm[];
    const uint32_t smb = smem_u32(sm);
    const int tid = threadIdx.x;
    const int wid = tid >> 5, lane = tid & 31;
    const int wr = wid >> 2, wc = wid & 3;
    const int which = blockIdx.y;
    const int m0 = blockIdx.x * 128;
    const __half* Wp = g_Wt[which];

    float acc[4][8][4];
#pragma unroll
    for (int i = 0; i < 4; i++)
#pragma unroll
        for (int j = 0; j < 8; j++)
#pragma unroll
            for (int q = 0; q < 4; q++) acc[i][j][q] = 0.f;

    auto issue_a = [&](int c, int buf) {
#pragma unroll
        for (int it = 0; it < 4; it++) {
            int idx = tid + it * 256;      // 1024 granules: 2 terms x 128 rows x 4
            int t = idx >> 9, rem = idx & 511;
            int r = rem >> 2, u = rem & 3;
            cp_async16(smb + a_off(buf, t) + sw64((uint32_t)(r * 64 + u * 16)),
                       g_Xh[t] + (size_t)(m0 + r) * NC + (size_t)c * 32 + u * 8);
        }
    };
    auto issue_b = [&](int c, int buf) {
#pragma unroll
        for (int it = 0; it < 8; it++) {
            int idx = tid + it * 256;      // 2048 granules: 2 terms x 256 rows x 4
            int t = idx >> 10, rem = idx & 1023;
            int n = rem >> 2, u = rem & 3;
            cp_async16(smb + b_off(buf, t) + sw64((uint32_t)(n * 64 + u * 16)),
                       Wp + (size_t)t * NH * NC + (size_t)n * NC + (size_t)c * 32 + u * 8);
        }
    };

    issue_a(0, 0);
    issue_b(0, 0);
    CP_COMMIT();
    CP_WAIT0();
    __syncthreads();

    const int KT = NC / 32;   // 64
    for (int c = 0; c < KT; c++) {
        const int cur = c & 1;
        if (c + 1 < KT) {
            issue_a(c + 1, cur ^ 1);
            issue_b(c + 1, cur ^ 1);
            CP_COMMIT();
        }
        mma_chunk3(smb, cur, wr, wc, lane, acc);
        if (c + 1 < KT) CP_WAIT0();
        __syncthreads();
    }

    const float inv = 1.0f / 64.0f;   // undo W prescale
    if (which == 2) {
#pragma unroll
        for (int mi = 0; mi < 4; mi++) {
            int m = m0 + wr * 64 + mi * 16 + (lane >> 2);
#pragma unroll
            for (int jj = 0; jj < 8; jj++) {
                int n = wc * 64 + jj * 8 + (lane & 3) * 2;
                *(float2*)(g_V + (size_t)m * NH + n) =
                    make_float2(acc[mi][jj][0] * inv, acc[mi][jj][1] * inv);
                *(float2*)(g_V + (size_t)(m + 8) * NH + n) =
                    make_float2(acc[mi][jj][2] * inv, acc[mi][jj][3] * inv);
            }
        }
    } else {
        __half* H1 = (which == 0) ? g_Kh[0] : g_Qh[0];
        __half* H2 = (which == 0) ? g_Kh[1] : g_Qh[1];
        auto store2 = [&](int m, int n, float a, float b) {
            __half a1 = __float2half_rn(a), b1 = __float2half_rn(b);
            __half a2 = __float2half_rn(a - __half2float(a1));
            __half b2 = __float2half_rn(b - __half2float(b1));
            *(__half2*)(H1 + (size_t)m * NH + n) = __halves2half2(a1, b1);
            *(__half2*)(H2 + (size_t)m * NH + n) = __halves2half2(a2, b2);
        };
#pragma unroll
        for (int mi = 0; mi < 4; mi++) {
            int m = m0 + wr * 64 + mi * 16 + (lane >> 2);
#pragma unroll
            for (int jj = 0; jj < 8; jj++) {
                int n = wc * 64 + jj * 8 + (lane & 3) * 2;
                store2(m, n, acc[mi][jj][0] * inv, acc[mi][jj][1] * inv);
                store2(m + 8, n, acc[mi][jj][2] * inv, acc[mi][jj][3] * inv);
            }
        }
    }
}

// ---------------------------------------------------------------------------
// Kernel 2: logits (fp16 split MMA).  L[b][j][i] = sqrt(C) * Q[b][j].K[b][i]
// M=128 (j), N=256 (i), K=256 (h). Triangular block skip; masked -> -inf.
// ---------------------------------------------------------------------------
__global__ void __launch_bounds__(256, 1) logits_h_kernel()
{
    const int bi = blockIdx.x, bj = blockIdx.y, b = blockIdx.z;
    if (bi * 256 + 256 <= bj * 128) return;   // whole block strictly below diagonal
    const int j0 = bj * 128;
    const int i0 = bi * 256;
    const size_t rowb = (size_t)b * NT;

    extern __shared__ char sm[];
    const uint32_t smb = smem_u32(sm);
    const int tid = threadIdx.x;
    const int wid = tid >> 5, lane = tid & 31;
    const int wr = wid >> 2, wc = wid & 3;

    float acc[4][8][4];
#pragma unroll
    for (int i = 0; i < 4; i++)
#pragma unroll
        for (int j = 0; j < 8; j++)
#pragma unroll
            for (int q = 0; q < 4; q++) acc[i][j][q] = 0.f;

    auto issue_a = [&](int c, int buf) {
#pragma unroll
        for (int it = 0; it < 4; it++) {
            int idx = tid + it * 256;
            int t = idx >> 9, rem = idx & 511;
            int r = rem >> 2, u = rem & 3;
            cp_async16(smb + a_off(buf, t) + sw64((uint32_t)(r * 64 + u * 16)),
                       g_Qh[t] + (rowb + j0 + r) * NH + (size_t)c * 32 + u * 8);
        }
    };
    auto issue_b = [&](int c, int buf) {
#pragma unroll
        for (int it = 0; it < 8; it++) {
            int idx = tid + it * 256;
            int t = idx >> 10, rem = idx & 1023;
            int n = rem >> 2, u = rem & 3;
            cp_async16(smb + b_off(buf, t) + sw64((uint32_t)(n * 64 + u * 16)),
                       g_Kh[t] + (rowb + i0 + n) * NH + (size_t)c * 32 + u * 8);
        }
    };

    issue_a(0, 0);
    issue_b(0, 0);
    CP_COMMIT();
    CP_WAIT0();
    __syncthreads();

    const int KT = NH / 32;   // 8
    for (int c = 0; c < KT; c++) {
        const int cur = c & 1;
        if (c + 1 < KT) {
            issue_a(c + 1, cur ^ 1);
            issue_b(c + 1, cur ^ 1);
            CP_COMMIT();
        }
        mma_chunk3(smb, cur, wr, wc, lane, acc);
        if (c + 1 < KT) CP_WAIT0();
        __syncthreads();
    }

    const float scale = 45.25483399593904f;  // sqrt(2048)
    float* Lb = g_L + (size_t)b * NT * NT;
#pragma unroll
    for (int mi = 0; mi < 4; mi++) {
        int m = wr * 64 + mi * 16 + (lane >> 2);
#pragma unroll
        for (int jj = 0; jj < 8; jj++) {
            int n = wc * 64 + jj * 8 + (lane & 3) * 2;
            int ig = i0 + n;
            {
                int jg = j0 + m;
                float2 v;
                v.x = (ig >= jg) ? acc[mi][jj][0] * scale : -INFINITY;
                v.y = (ig + 1 >= jg) ? acc[mi][jj][1] * scale : -INFINITY;
                *(float2*)(Lb + (size_t)jg * NT + ig) = v;
            }
            {
                int jg = j0 + m + 8;
                float2 v;
                v.x = (ig >= jg) ? acc[mi][jj][2] * scale : -INFINITY;
                v.y = (ig + 1 >= jg) ? acc[mi][jj][3] * scale : -INFINITY;
                *(float2*)(Lb + (size_t)jg * NT + ig) = v;
            }
        }
    }
}

// ---------------------------------------------------------------------------
// Kernel 3: per-column softmax stats (rows of L): m_j, 1/sum_j
// ---------------------------------------------------------------------------
__global__ void __launch_bounds__(128) stats_kernel()
{
    const int j = blockIdx.x, b = blockIdx.y;
    const float* row = g_L + (size_t)b * NT * NT + (size_t)j * NT;
    const int tid = threadIdx.x;

    float mx = -INFINITY;
    for (int i = j + tid; i < NT; i += 128) mx = fmaxf(mx, row[i]);
#pragma unroll
    for (int o = 16; o > 0; o >>= 1) mx = fmaxf(mx, __shfl_xor_sync(0xffffffffu, mx, o));

    __shared__ float redm[4];
    __shared__ float reds[4];
    const int w = tid >> 5, lane = tid & 31;
    if (lane == 0) redm[w] = mx;
    __syncthreads();
    mx = fmaxf(fmaxf(redm[0], redm[1]), fmaxf(redm[2], redm[3]));

    float s = 0.f;
    for (int i = j + tid; i < NT; i += 128) s += __expf(row[i] - mx);
#pragma unroll
    for (int o = 16; o > 0; o >>= 1) s += __shfl_xor_sync(0xffffffffu, s, o);
    if (lane == 0) reds[w] = s;
    __syncthreads();
    if (tid == 0) {
        s = reds[0] + reds[1] + reds[2] + reds[3];
        g_m[b * NT + j] = mx;
        g_rs[b * NT + j] = 1.0f / s;
    }
}

// ---------------------------------------------------------------------------
// Kernel 4: out[b][i][h] = sum_{j<=i} exp(L[j][i]-m_j)/s_j * V[b][j][h]
// ---------------------------------------------------------------------------
__global__ void __launch_bounds__(256) av_kernel(float* __restrict__ Out)
{
    const int BK = 16;
    const int b = blockIdx.z;
    const int i0 = blockIdx.y * 128;
    const int h0 = blockIdx.x * 128;
    const float* Lb = g_L + (size_t)b * NT * NT;
    const float* Vb = g_V + (size_t)b * NT * NH;
    const float* mb = g_m + b * NT;
    const float* rb = g_rs + b * NT;

    __shared__ float Ps[2][BK][128];
    __shared__ float Vs[2][BK][128];

    const int tid = threadIdx.x;
    const int prow = tid >> 5;
    const int pcol = (tid & 31) << 2;
    const int tx = tid & 15, ty = tid >> 4;

    float acc[8][8];
#pragma unroll
    for (int i = 0; i < 8; i++)
#pragma unroll
        for (int j = 0; j < 8; j++) acc[i][j] = 0.f;

    const int KT = (i0 + 128) / BK;

    {
#pragma unroll
        for (int it = 0; it < 2; it++) {
            int jg = prow + it * 8;
            float4 lv = *(const float4*)(Lb + (size_t)jg * NT + i0 + pcol);
            float mj = mb[jg], rj = rb[jg];
            float4 p;
            p.x = __expf(lv.x - mj) * rj;
            p.y = __expf(lv.y - mj) * rj;
            p.z = __expf(lv.z - mj) * rj;
            p.w = __expf(lv.w - mj) * rj;
            *(float4*)&Ps[0][prow + it * 8][pcol] = p;
            *(float4*)&Vs[0][prow + it * 8][pcol] =
                *(const float4*)(Vb + (size_t)jg * NH + h0 + pcol);
        }
    }
    __syncthreads();

    for (int t = 0; t < KT; t++) {
        int cur = t & 1;
        float4 pv0, pv1, vv0, vv1;
        if (t + 1 < KT) {
            int j0 = (t + 1) * BK;
            int jg0 = j0 + prow, jg1 = j0 + prow + 8;
            float4 l0 = *(const float4*)(Lb + (size_t)jg0 * NT + i0 + pcol);
            float4 l1 = *(const float4*)(Lb + (size_t)jg1 * NT + i0 + pcol);
            float m0 = mb[jg0], r0 = rb[jg0];
            float m1 = mb[jg1], r1 = rb[jg1];
            pv0.x = __expf(l0.x - m0) * r0; pv0.y = __expf(l0.y - m0) * r0;
            pv0.z = __expf(l0.z - m0) * r0; pv0.w = __expf(l0.w - m0) * r0;
            pv1.x = __expf(l1.x - m1) * r1; pv1.y = __expf(l1.y - m1) * r1;
            pv1.z = __expf(l1.z - m1) * r1; pv1.w = __expf(l1.w - m1) * r1;
            vv0 = *(const float4*)(Vb + (size_t)jg0 * NH + h0 + pcol);
            vv1 = *(const float4*)(Vb + (size_t)jg1 * NH + h0 + pcol);
        }
#pragma unroll
        for (int k = 0; k < BK; k++) {
            float a[8], bb[8];
            *(float4*)&a[0] = *(const float4*)&Ps[cur][k][ty * 8];
            *(float4*)&a[4] = *(const float4*)&Ps[cur][k][ty * 8 + 4];
            *(float4*)&bb[0] = *(const float4*)&Vs[cur][k][tx * 8];
            *(float4*)&bb[4] = *(const float4*)&Vs[cur][k][tx * 8 + 4];
#pragma unroll
            for (int i = 0; i < 8; i++)
#pragma unroll
                for (int j = 0; j < 8; j++)
                    acc[i][j] = fmaf(a[i], bb[j], acc[i][j]);
        }
        if (t + 1 < KT) {
            int nxt = cur ^ 1;
            *(float4*)&Ps[nxt][prow][pcol] = pv0;
            *(float4*)&Ps[nxt][prow + 8][pcol] = pv1;
            *(float4*)&Vs[nxt][prow][pcol] = vv0;
            *(float4*)&Vs[nxt][prow + 8][pcol] = vv1;
        }
        __syncthreads();
    }

    float* Op = Out + (size_t)(b * NT + i0 + ty * 8) * NH + h0 + tx * 8;
#pragma unroll
    for (int i = 0; i < 8; i++) {
        *(float4*)(Op + (size_t)i * NH) =
            make_float4(acc[i][0], acc[i][1], acc[i][2], acc[i][3]);
        *(float4*)(Op + (size_t)i * NH + 4) =
            make_float4(acc[i][4], acc[i][5], acc[i][6], acc[i][7]);
    }
}

// ---------------------------------------------------------------------------
extern "C" void kernel_launch(void* const* d_in, const int* in_sizes, int n_in,
                              void* d_out, int out_size)
{
    const float* X  = (const float*)d_in[0];   // token_embd [16,2048,2048]
    const float* Wk = (const float*)d_in[1];   // [2048,256]
    const float* Wq = (const float*)d_in[2];
    const float* Wv = (const float*)d_in[3];
    float* out = (float*)d_out;                // [16,2048,256] fp32

    cudaFuncSetAttribute(proj_h_kernel,
                         cudaFuncAttributeMaxDynamicSharedMemorySize, GEMM_SMEM);
    cudaFuncSetAttribute(logits_h_kernel,
                         cudaFuncAttributeMaxDynamicSharedMemorySize, GEMM_SMEM);

    xsplit_kernel<<<8192, 256>>>(X);
    wprep_kernel<<<dim3(NC / 32, NH / 32, 3), dim3(32, 8)>>>(Wk, Wq, Wv);

    proj_h_kernel<<<dim3(BTOT / 128, 3), 256, GEMM_SMEM>>>();

    logits_h_kernel<<<dim3(NT / 256, NT / 128, NB), 256, GEMM_SMEM>>>();

    stats_kernel<<<dim3(NT, NB), 128>>>();

    av_kernel<<<dim3(NH / 128, NT / 128, NB), 256>>>(out);
}

// round 10
// speedup vs baseline: 2.5772x; 1.2053x over previous
#include <cuda_runtime.h>
#include <cuda_fp16.h>
#include <math.h>
#include <stdint.h>

#define NB 16
#define NT 2048
#define NC 2048
#define NH 256
#define BTOT (NB * NT)   // 32768 rows

// Scratch (device globals: allocation-free per harness rules)
__device__ float g_L[NB * NT * NT];         // 268 MB, L[b][i][j] = k_i . q_j * sqrt(C)
__device__ float g_m[BTOT];                 // per (b,j) column max
__device__ float g_rs[BTOT];                // per (b,j) 1/sum
__device__ __half g_Wt[3][2 * NH * NC];     // W*64 transposed, 2-term split
__device__ __half g_Kh[2][BTOT * NH];       // K fp16 2-term split
__device__ __half g_Qh[2][BTOT * NH];       // Q fp16 2-term split
__device__ __half g_Vh[BTOT * NH];          // V fp16 [b*NT+j][h]
__device__ __half g_Vth[NB * NH * NT];      // V^T fp16 [b][h][j]

// ---------------------------------------------------------------------------
__device__ __forceinline__ uint32_t smem_u32(const void* p) {
    uint32_t a;
    asm("{ .reg .u64 t; cvta.to.shared.u64 t, %1; cvt.u32.u64 %0, t; }"
        : "=r"(a) : "l"(p));
    return a;
}
__device__ __forceinline__ uint32_t sw64(uint32_t o) { return o ^ ((o >> 3) & 0x30); }

__device__ __forceinline__ void ldsm_x4(uint32_t& r0, uint32_t& r1, uint32_t& r2,
                                        uint32_t& r3, uint32_t addr) {
    asm volatile("ldmatrix.sync.aligned.m8n8.x4.shared.b16 {%0,%1,%2,%3}, [%4];"
                 : "=r"(r0), "=r"(r1), "=r"(r2), "=r"(r3) : "r"(addr));
}
__device__ __forceinline__ void mma_h(float* d, uint32_t a0, uint32_t a1,
                                      uint32_t a2, uint32_t a3,
                                      uint32_t b0, uint32_t b1) {
    asm volatile(
        "mma.sync.aligned.m16n8k16.row.col.f32.f16.f16.f32 "
        "{%0,%1,%2,%3}, {%4,%5,%6,%7}, {%8,%9}, {%0,%1,%2,%3};"
        : "+f"(d[0]), "+f"(d[1]), "+f"(d[2]), "+f"(d[3])
        : "r"(a0), "r"(a1), "r"(a2), "r"(a3), "r"(b0), "r"(b1));
}
__device__ __forceinline__ void cp_async16(uint32_t dst, const void* src) {
    asm volatile("cp.async.cg.shared.global [%0], [%1], 16;"
                 :: "r"(dst), "l"(src) : "memory");
}
#define CP_COMMIT() asm volatile("cp.async.commit_group;" ::: "memory")
#define CP_WAIT0()  asm volatile("cp.async.wait_group 0;" ::: "memory")

// SMEM layout for proj & logits (2-term): A 2x8KB, B 2x16KB, double buffered.
#define A_T 8192
#define B_T 16384
#define STG (2 * A_T + 2 * B_T)     // 49152
#define GEMM_SMEM (2 * STG)         // 98304
__device__ __forceinline__ uint32_t a_off(int buf, int t) { return buf * STG + t * A_T; }
__device__ __forceinline__ uint32_t b_off(int buf, int t) { return buf * STG + 2 * A_T + t * B_T; }

// av (1-term): A 8KB, B 16KB per stage.
#define AV_STG (A_T + B_T)          // 24576
#define AV_SMEM (2 * AV_STG)        // 49152

// 3-product fp16 split MMA over one 32-wide K chunk (terms: a1b1, a1b2, a2b1)
__device__ __forceinline__ void mma_chunk3(uint32_t smb, int buf, int wr, int wc,
                                           int lane, float (*acc)[8][4]) {
    const int TA[3] = {0, 0, 1};
    const int TB[3] = {0, 1, 0};
#pragma unroll
    for (int ks = 0; ks < 2; ks++) {
        const uint32_t kb = ks * 32;
        const uint32_t a_row = (uint32_t)((wr * 64 + (lane & 15)) * 64) + kb + (lane >> 4) * 16;
        const uint32_t b_row = (uint32_t)((wc * 64 + (lane & 7) + ((lane >> 4) & 1) * 8) * 64) +
                               kb + ((lane >> 3) & 1) * 16;
#pragma unroll
        for (int p = 0; p < 3; p++) {
            const uint32_t abase = smb + a_off(buf, TA[p]);
            uint32_t af4[4][4];
#pragma unroll
            for (int mi = 0; mi < 4; mi++)
                ldsm_x4(af4[mi][0], af4[mi][1], af4[mi][2], af4[mi][3],
                        abase + sw64(a_row + (uint32_t)(mi * 16 * 64)));
            const uint32_t bbase = smb + b_off(buf, TB[p]);
#pragma unroll
            for (int nj = 0; nj < 4; nj++) {
                uint32_t b4[4];
                ldsm_x4(b4[0], b4[1], b4[2], b4[3],
                        bbase + sw64(b_row + (uint32_t)(nj * 16 * 64)));
#pragma unroll
                for (int mi = 0; mi < 4; mi++) {
                    mma_h(acc[mi][2 * nj], af4[mi][0], af4[mi][1], af4[mi][2], af4[mi][3],
                          b4[0], b4[1]);
                    mma_h(acc[mi][2 * nj + 1], af4[mi][0], af4[mi][1], af4[mi][2], af4[mi][3],
                          b4[2], b4[3]);
                }
            }
        }
    }
}

// single-product fp16 MMA over one 32-wide K chunk
__device__ __forceinline__ void mma_chunk1(uint32_t a_base, uint32_t b_base,
                                           int wr, int wc, int lane, float (*acc)[8][4]) {
#pragma unroll
    for (int ks = 0; ks < 2; ks++) {
        const uint32_t kb = ks * 32;
        const uint32_t a_row = (uint32_t)((wr * 64 + (lane & 15)) * 64) + kb + (lane >> 4) * 16;
        const uint32_t b_row = (uint32_t)((wc * 64 + (lane & 7) + ((lane >> 4) & 1) * 8) * 64) +
                               kb + ((lane >> 3) & 1) * 16;
        uint32_t af4[4][4];
#pragma unroll
        for (int mi = 0; mi < 4; mi++)
            ldsm_x4(af4[mi][0], af4[mi][1], af4[mi][2], af4[mi][3],
                    a_base + sw64(a_row + (uint32_t)(mi * 16 * 64)));
#pragma unroll
        for (int nj = 0; nj < 4; nj++) {
            uint32_t b4[4];
            ldsm_x4(b4[0], b4[1], b4[2], b4[3],
                    b_base + sw64(b_row + (uint32_t)(nj * 16 * 64)));
#pragma unroll
            for (int mi = 0; mi < 4; mi++) {
                mma_h(acc[mi][2 * nj], af4[mi][0], af4[mi][1], af4[mi][2], af4[mi][3],
                      b4[0], b4[1]);
                mma_h(acc[mi][2 * nj + 1], af4[mi][0], af4[mi][1], af4[mi][2], af4[mi][3],
                      b4[2], b4[3]);
            }
        }
    }
}

// ---------------------------------------------------------------------------
// Kernel 0: weights: transpose, scale x64 (avoid fp16 subnormals), 2-term split
// ---------------------------------------------------------------------------
__global__ void wprep_kernel(const float* __restrict__ Wk,
                             const float* __restrict__ Wq,
                             const float* __restrict__ Wv)
{
    const float* W = (blockIdx.z == 0) ? Wk : (blockIdx.z == 1) ? Wq : Wv;
    __half* dst = g_Wt[blockIdx.z];
    __shared__ float tile[32][33];
    int k0 = blockIdx.x * 32, n0 = blockIdx.y * 32;
    int tx = threadIdx.x, ty = threadIdx.y;  // (32, 8)
#pragma unroll
    for (int i = 0; i < 32; i += 8)
        tile[ty + i][tx] = W[(size_t)(k0 + ty + i) * NH + n0 + tx];
    __syncthreads();
#pragma unroll
    for (int i = 0; i < 32; i += 8) {
        int n = n0 + ty + i, k = k0 + tx;
        float w = tile[tx][ty + i] * 64.0f;
        __half h1 = __float2half_rn(w);
        __half h2 = __float2half_rn(w - __half2float(h1));
        size_t o = (size_t)n * NC + k;
        dst[o] = h1;
        dst[(size_t)NH * NC + o] = h2;
    }
}

// ---------------------------------------------------------------------------
// Kernel 1: projection.  In-loader fp16 2-split of X; 3-product MMA.
// which = blockIdx.y: 0=K 1=Q (epilogue -> fp16 split pair), 2=V (-> fp16).
// ---------------------------------------------------------------------------
__global__ void __launch_bounds__(256, 1) proj_h_kernel(const float* __restrict__ X)
{
    extern __shared__ char sm[];
    const uint32_t smb = smem_u32(sm);
    const int tid = threadIdx.x;
    const int wid = tid >> 5, lane = tid & 31;
    const int wr = wid >> 2, wc = wid & 3;
    const int which = blockIdx.y;
    const int m0 = blockIdx.x * 128;
    const __half* Wp = g_Wt[which];
    const int ar = tid >> 3, au = tid & 7;   // A loader: row base, float4 slot

    float acc[4][8][4];
#pragma unroll
    for (int i = 0; i < 4; i++)
#pragma unroll
        for (int j = 0; j < 8; j++)
#pragma unroll
            for (int q = 0; q < 4; q++) acc[i][j][q] = 0.f;

    auto load_x = [&](int c, float4* xv) {
        const float* Xp = X + (size_t)m0 * NC + (size_t)c * 32;
#pragma unroll
        for (int it = 0; it < 4; it++)
            xv[it] = *(const float4*)(Xp + (size_t)(ar + it * 32) * NC + au * 4);
    };
    auto store_a = [&](int buf, const float4* xv) {
#pragma unroll
        for (int it = 0; it < 4; it++) {
            __half x1 = __float2half_rn(xv[it].x), y1 = __float2half_rn(xv[it].y);
            __half z1 = __float2half_rn(xv[it].z), w1 = __float2half_rn(xv[it].w);
            __half x2 = __float2half_rn(xv[it].x - __half2float(x1));
            __half y2 = __float2half_rn(xv[it].y - __half2float(y1));
            __half z2 = __float2half_rn(xv[it].z - __half2float(z1));
            __half w2 = __float2half_rn(xv[it].w - __half2float(w1));
            uint32_t off = sw64((uint32_t)((ar + it * 32) * 64 + au * 8));
            *(uint2*)(sm + a_off(buf, 0) + off) =
                make_uint2((uint32_t)__half_as_ushort(x1) | ((uint32_t)__half_as_ushort(y1) << 16),
                           (uint32_t)__half_as_ushort(z1) | ((uint32_t)__half_as_ushort(w1) << 16));
            *(uint2*)(sm + a_off(buf, 1) + off) =
                make_uint2((uint32_t)__half_as_ushort(x2) | ((uint32_t)__half_as_ushort(y2) << 16),
                           (uint32_t)__half_as_ushort(z2) | ((uint32_t)__half_as_ushort(w2) << 16));
        }
    };
    auto issue_b = [&](int c, int buf) {
#pragma unroll
        for (int it = 0; it < 8; it++) {
            int idx = tid + it * 256;      // 2048 granules: 2 terms x 256 rows x 4
            int t = idx >> 10, rem = idx & 1023;
            int n = rem >> 2, u = rem & 3;
            cp_async16(smb + b_off(buf, t) + sw64((uint32_t)(n * 64 + u * 16)),
                       Wp + (size_t)t * NH * NC + (size_t)n * NC + (size_t)c * 32 + u * 8);
        }
        CP_COMMIT();
    };

    {
        float4 xv[4];
        load_x(0, xv);
        issue_b(0, 0);
        store_a(0, xv);
        CP_WAIT0();
        __syncthreads();
    }

    const int KT = NC / 32;   // 64
    for (int c = 0; c < KT; c++) {
        const int cur = c & 1;
        float4 xv[4];
        if (c + 1 < KT) {
            issue_b(c + 1, cur ^ 1);
            load_x(c + 1, xv);
        }
        mma_chunk3(smb, cur, wr, wc, lane, acc);
        if (c + 1 < KT) {
            store_a(cur ^ 1, xv);
            CP_WAIT0();
        }
        __syncthreads();
    }

    const float inv = 1.0f / 64.0f;   // undo W prescale
    if (which == 2) {
#pragma unroll
        for (int mi = 0; mi < 4; mi++) {
            int m = m0 + wr * 64 + mi * 16 + (lane >> 2);
#pragma unroll
            for (int jj = 0; jj < 8; jj++) {
                int n = wc * 64 + jj * 8 + (lane & 3) * 2;
                *(__half2*)(g_Vh + (size_t)m * NH + n) =
                    __halves2half2(__float2half_rn(acc[mi][jj][0] * inv),
                                   __float2half_rn(acc[mi][jj][1] * inv));
                *(__half2*)(g_Vh + (size_t)(m + 8) * NH + n) =
                    __halves2half2(__float2half_rn(acc[mi][jj][2] * inv),
                                   __float2half_rn(acc[mi][jj][3] * inv));
            }
        }
    } else {
        __half* H1 = (which == 0) ? g_Kh[0] : g_Qh[0];
        __half* H2 = (which == 0) ? g_Kh[1] : g_Qh[1];
        auto store2 = [&](int m, int n, float a, float b) {
            __half a1 = __float2half_rn(a), b1 = __float2half_rn(b);
            __half a2 = __float2half_rn(a - __half2float(a1));
            __half b2 = __float2half_rn(b - __half2float(b1));
            *(__half2*)(H1 + (size_t)m * NH + n) = __halves2half2(a1, b1);
            *(__half2*)(H2 + (size_t)m * NH + n) = __halves2half2(a2, b2);
        };
#pragma unroll
        for (int mi = 0; mi < 4; mi++) {
            int m = m0 + wr * 64 + mi * 16 + (lane >> 2);
#pragma unroll
            for (int jj = 0; jj < 8; jj++) {
                int n = wc * 64 + jj * 8 + (lane & 3) * 2;
                store2(m, n, acc[mi][jj][0] * inv, acc[mi][jj][1] * inv);
                store2(m + 8, n, acc[mi][jj][2] * inv, acc[mi][jj][3] * inv);
            }
        }
    }
}

// ---------------------------------------------------------------------------
// Kernel 1b: V transpose: g_Vth[b][h][j] = g_Vh[b*NT+j][h]
// ---------------------------------------------------------------------------
__global__ void vtrans_kernel()
{
    __shared__ __half t[32][33];
    int b = blockIdx.z, j0 = blockIdx.x * 32, h0 = blockIdx.y * 32;
    int tx = threadIdx.x, ty = threadIdx.y;   // (32, 8)
    const __half* src = g_Vh + ((size_t)b * NT + j0) * NH + h0;
#pragma unroll
    for (int i = 0; i < 4; i++)
        t[ty + i * 8][tx] = src[(size_t)(ty + i * 8) * NH + tx];
    __syncthreads();
    __half* dst = g_Vth + ((size_t)b * NH + h0) * NT + j0;
#pragma unroll
    for (int i = 0; i < 4; i++)
        dst[(size_t)(ty + i * 8) * NT + tx] = t[tx][ty + i * 8];
}

// ---------------------------------------------------------------------------
// Kernel 2: logits.  L[b][i][j] = sqrt(C) * K[b][i] . Q[b][j]
// M=128 (i), N=256 (j), K=256 (h). Keep i >= j; else -inf. Skip all-masked blocks.
// ---------------------------------------------------------------------------
__global__ void __launch_bounds__(256, 1) logits_h_kernel()
{
    const int bx = blockIdx.x, by = blockIdx.y, b = blockIdx.z;
    if (bx * 128 + 128 <= by * 256) return;   // all i < j: fully masked, never read
    const int i0 = bx * 128;
    const int j0 = by * 256;
    const size_t rowb = (size_t)b * NT;

    extern __shared__ char sm[];
    const uint32_t smb = smem_u32(sm);
    const int tid = threadIdx.x;
    const int wid = tid >> 5, lane = tid & 31;
    const int wr = wid >> 2, wc = wid & 3;

    float acc[4][8][4];
#pragma unroll
    for (int i = 0; i < 4; i++)
#pragma unroll
        for (int j = 0; j < 8; j++)
#pragma unroll
            for (int q = 0; q < 4; q++) acc[i][j][q] = 0.f;

    auto issue_a = [&](int c, int buf) {
#pragma unroll
        for (int it = 0; it < 4; it++) {
            int idx = tid + it * 256;
            int t = idx >> 9, rem = idx & 511;
            int r = rem >> 2, u = rem & 3;
            cp_async16(smb + a_off(buf, t) + sw64((uint32_t)(r * 64 + u * 16)),
                       g_Kh[t] + (rowb + i0 + r) * NH + (size_t)c * 32 + u * 8);
        }
    };
    auto issue_b = [&](int c, int buf) {
#pragma unroll
        for (int it = 0; it < 8; it++) {
            int idx = tid + it * 256;
            int t = idx >> 10, rem = idx & 1023;
            int n = rem >> 2, u = rem & 3;
            cp_async16(smb + b_off(buf, t) + sw64((uint32_t)(n * 64 + u * 16)),
                       g_Qh[t] + (rowb + j0 + n) * NH + (size_t)c * 32 + u * 8);
        }
    };

    issue_a(0, 0);
    issue_b(0, 0);
    CP_COMMIT();
    CP_WAIT0();
    __syncthreads();

    const int KT = NH / 32;   // 8
    for (int c = 0; c < KT; c++) {
        const int cur = c & 1;
        if (c + 1 < KT) {
            issue_a(c + 1, cur ^ 1);
            issue_b(c + 1, cur ^ 1);
            CP_COMMIT();
        }
        mma_chunk3(smb, cur, wr, wc, lane, acc);
        if (c + 1 < KT) CP_WAIT0();
        __syncthreads();
    }

    const float scale = 45.25483399593904f;  // sqrt(2048)
    float* Lb = g_L + (size_t)b * NT * NT;
#pragma unroll
    for (int mi = 0; mi < 4; mi++) {
        int m = wr * 64 + mi * 16 + (lane >> 2);
#pragma unroll
        for (int jj = 0; jj < 8; jj++) {
            int n = wc * 64 + jj * 8 + (lane & 3) * 2;
            int jg = j0 + n;
            {
                int ig = i0 + m;
                float2 v;
                v.x = (ig >= jg) ? acc[mi][jj][0] * scale : -INFINITY;
                v.y = (ig >= jg + 1) ? acc[mi][jj][1] * scale : -INFINITY;
                *(float2*)(Lb + (size_t)ig * NT + jg) = v;
            }
            {
                int ig = i0 + m + 8;
                float2 v;
                v.x = (ig >= jg) ? acc[mi][jj][2] * scale : -INFINITY;
                v.y = (ig >= jg + 1) ? acc[mi][jj][3] * scale : -INFINITY;
                *(float2*)(Lb + (size_t)ig * NT + jg) = v;
            }
        }
    }
}

// ---------------------------------------------------------------------------
// Kernel 3: softmax stats.  Column j owned by one thread; coalesced row loads.
// m_j = max_i L[i][j], rs_j = 1/sum exp. Start at i = j0 (rows below are unwritten
// only when fully masked; all i >= j0 rows of these columns are written).
// ---------------------------------------------------------------------------
__global__ void __launch_bounds__(128) stats_kernel()
{
    const int j0 = blockIdx.x * 128, b = blockIdx.y;
    const int j = j0 + threadIdx.x;
    const float* base = g_L + (size_t)b * NT * NT + j;

    float m = -INFINITY;
    for (int i = j0; i < NT; i += 4) {
        float a0 = base[(size_t)i * NT];
        float a1 = base[(size_t)(i + 1) * NT];
        float a2 = base[(size_t)(i + 2) * NT];
        float a3 = base[(size_t)(i + 3) * NT];
        m = fmaxf(m, fmaxf(fmaxf(a0, a1), fmaxf(a2, a3)));
    }
    float s = 0.f;
    for (int i = j0; i < NT; i += 4) {
        float a0 = base[(size_t)i * NT];
        float a1 = base[(size_t)(i + 1) * NT];
        float a2 = base[(size_t)(i + 2) * NT];
        float a3 = base[(size_t)(i + 3) * NT];
        s += __expf(a0 - m) + __expf(a1 - m) + __expf(a2 - m) + __expf(a3 - m);
    }
    g_m[b * NT + j] = m;
    g_rs[b * NT + j] = 1.0f / s;
}

// ---------------------------------------------------------------------------
// Kernel 4: av (fp16 MMA).  out[b][i][h] = sum_{j<=i} P[i][j] * V[j][h]
// A = P (exp fused in loader), B = V^T. M=128 i, N=256 h, K = j (triangular).
// ---------------------------------------------------------------------------
__global__ void __launch_bounds__(256, 1) av_h_kernel(float* __restrict__ Out)
{
    extern __shared__ char sm[];
    const uint32_t smb = smem_u32(sm);
    const int tid = threadIdx.x;
    const int wid = tid >> 5, lane = tid & 31;
    const int wr = wid >> 2, wc = wid & 3;
    const int b = blockIdx.y;
    const int i0 = (gridDim.x - 1 - blockIdx.x) * 128;   // big tiles first
    const float* Lb = g_L + (size_t)b * NT * NT;
    const float* mb = g_m + b * NT;
    const float* rb = g_rs + b * NT;
    const __half* Vt = g_Vth + (size_t)b * NH * NT;
    const int ar = tid >> 3, au = tid & 7;

    float acc[4][8][4];
#pragma unroll
    for (int i = 0; i < 4; i++)
#pragma unroll
        for (int j = 0; j < 8; j++)
#pragma unroll
            for (int q = 0; q < 4; q++) acc[i][j][q] = 0.f;

    auto load_p = [&](int c, float4* lv, float4& m4, float4& r4) {
        m4 = *(const float4*)(mb + c * 32 + au * 4);
        r4 = *(const float4*)(rb + c * 32 + au * 4);
#pragma unroll
        for (int it = 0; it < 4; it++)
            lv[it] = *(const float4*)(Lb + (size_t)(i0 + ar + it * 32) * NT +
                                      (size_t)c * 32 + au * 4);
    };
    auto store_p = [&](int buf, const float4* lv, const float4& m4, const float4& r4) {
#pragma unroll
        for (int it = 0; it < 4; it++) {
            __half px = __float2half_rn(__expf(lv[it].x - m4.x) * r4.x);
            __half py = __float2half_rn(__expf(lv[it].y - m4.y) * r4.y);
            __half pz = __float2half_rn(__expf(lv[it].z - m4.z) * r4.z);
            __half pw = __float2half_rn(__expf(lv[it].w - m4.w) * r4.w);
            uint32_t off = sw64((uint32_t)((ar + it * 32) * 64 + au * 8));
            *(uint2*)(sm + buf * AV_STG + off) =
                make_uint2((uint32_t)__half_as_ushort(px) | ((uint32_t)__half_as_ushort(py) << 16),
                           (uint32_t)__half_as_ushort(pz) | ((uint32_t)__half_as_ushort(pw) << 16));
        }
    };
    auto issue_v = [&](int c, int buf) {
#pragma unroll
        for (int it = 0; it < 4; it++) {
            int idx = tid + it * 256;      // 1024 granules: 256 rows x 4
            int n = idx >> 2, u = idx & 3;
            cp_async16(smb + buf * AV_STG + A_T + sw64((uint32_t)(n * 64 + u * 16)),
                       Vt + (size_t)n * NT + (size_t)c * 32 + u * 8);
        }
        CP_COMMIT();
    };

    const int KT = (i0 + 128) / 32;

    {
        float4 lv[4], m4, r4;
        load_p(0, lv, m4, r4);
        issue_v(0, 0);
        store_p(0, lv, m4, r4);
        CP_WAIT0();
        __syncthreads();
    }

    for (int c = 0; c < KT; c++) {
        const int cur = c & 1;
        float4 lv[4], m4, r4;
        if (c + 1 < KT) {
            issue_v(c + 1, cur ^ 1);
            load_p(c + 1, lv, m4, r4);
        }
        mma_chunk1(smb + cur * AV_STG, smb + cur * AV_STG + A_T, wr, wc, lane, acc);
        if (c + 1 < KT) {
            store_p(cur ^ 1, lv, m4, r4);
            CP_WAIT0();
        }
        __syncthreads();
    }

    float* Ob = Out + (size_t)b * NT * NH;
#pragma unroll
    for (int mi = 0; mi < 4; mi++) {
        int m = i0 + wr * 64 + mi * 16 + (lane >> 2);
#pragma unroll
        for (int jj = 0; jj < 8; jj++) {
            int n = wc * 64 + jj * 8 + (lane & 3) * 2;
            *(float2*)(Ob + (size_t)m * NH + n) = make_float2(acc[mi][jj][0], acc[mi][jj][1]);
            *(float2*)(Ob + (size_t)(m + 8) * NH + n) = make_float2(acc[mi][jj][2], acc[mi][jj][3]);
        }
    }
}

// ---------------------------------------------------------------------------
extern "C" void kernel_launch(void* const* d_in, const int* in_sizes, int n_in,
                              void* d_out, int out_size)
{
    const float* X  = (const float*)d_in[0];   // token_embd [16,2048,2048]
    const float* Wk = (const float*)d_in[1];   // [2048,256]
    const float* Wq = (const float*)d_in[2];
    const float* Wv = (const float*)d_in[3];
    float* out = (float*)d_out;                // [16,2048,256] fp32

    cudaFuncSetAttribute(proj_h_kernel,
                         cudaFuncAttributeMaxDynamicSharedMemorySize, GEMM_SMEM);
    cudaFuncSetAttribute(logits_h_kernel,
                         cudaFuncAttributeMaxDynamicSharedMemorySize, GEMM_SMEM);
    cudaFuncSetAttribute(av_h_kernel,
                         cudaFuncAttributeMaxDynamicSharedMemorySize, AV_SMEM);

    wprep_kernel<<<dim3(NC / 32, NH / 32, 3), dim3(32, 8)>>>(Wk, Wq, Wv);

    proj_h_kernel<<<dim3(BTOT / 128, 3), 256, GEMM_SMEM>>>(X);

    vtrans_kernel<<<dim3(NT / 32, NH / 32, NB), dim3(32, 8)>>>();

    logits_h_kernel<<<dim3(NT / 128, NT / 256, NB), 256, GEMM_SMEM>>>();

    stats_kernel<<<dim3(NT / 128, NB), 128>>>();

    av_h_kernel<<<dim3(NT / 128, NB), 256, AV_SMEM>>>(out);
}

// round 11
// speedup vs baseline: 3.4902x; 1.3542x over previous
#include <cuda_runtime.h>
#include <cuda_fp16.h>
#include <math.h>
#include <stdint.h>

#define NB 16
#define NT 2048
#define NC 2048
#define NH 256
#define BTOT (NB * NT)   // 32768 rows

// Scratch (device globals: allocation-free per harness rules)
__device__ float g_L[NB * NT * NT];         // 268 MB, L[b][i][j] = k_i . q_j * sqrt(C)
__device__ float g_m[BTOT];                 // per (b,j) column max
__device__ float g_rs[BTOT];                // per (b,j) 1/sum
__device__ float g_pm[NB * 32 * NT];        // partial col-max per 64-row slab
__device__ float g_ps[NB * 32 * NT];        // partial col-sum per 64-row slab
__device__ __half g_Wt[3][2 * NH * NC];     // W*64 transposed, 2-term split
__device__ __half g_Kh[2][BTOT * NH];       // K fp16 2-term split
__device__ __half g_Qh[2][BTOT * NH];       // Q fp16 2-term split
__device__ __half g_Vh[BTOT * NH];          // V fp16 [b*NT+j][h]
__device__ __half g_Vth[NB * NH * NT];      // V^T fp16 [b][h][j]

// ---------------------------------------------------------------------------
__device__ __forceinline__ uint32_t smem_u32(const void* p) {
    uint32_t a;
    asm("{ .reg .u64 t; cvta.to.shared.u64 t, %1; cvt.u32.u64 %0, t; }"
        : "=r"(a) : "l"(p));
    return a;
}
__device__ __forceinline__ uint32_t sw64(uint32_t o) { return o ^ ((o >> 3) & 0x30); }

__device__ __forceinline__ void ldsm_x4(uint32_t& r0, uint32_t& r1, uint32_t& r2,
                                        uint32_t& r3, uint32_t addr) {
    asm volatile("ldmatrix.sync.aligned.m8n8.x4.shared.b16 {%0,%1,%2,%3}, [%4];"
                 : "=r"(r0), "=r"(r1), "=r"(r2), "=r"(r3) : "r"(addr));
}
__device__ __forceinline__ void mma_h(float* d, uint32_t a0, uint32_t a1,
                                      uint32_t a2, uint32_t a3,
                                      uint32_t b0, uint32_t b1) {
    asm volatile(
        "mma.sync.aligned.m16n8k16.row.col.f32.f16.f16.f32 "
        "{%0,%1,%2,%3}, {%4,%5,%6,%7}, {%8,%9}, {%0,%1,%2,%3};"
        : "+f"(d[0]), "+f"(d[1]), "+f"(d[2]), "+f"(d[3])
        : "r"(a0), "r"(a1), "r"(a2), "r"(a3), "r"(b0), "r"(b1));
}
__device__ __forceinline__ void cp_async16(uint32_t dst, const void* src) {
    asm volatile("cp.async.cg.shared.global [%0], [%1], 16;"
                 :: "r"(dst), "l"(src) : "memory");
}
#define CP_COMMIT() asm volatile("cp.async.commit_group;" ::: "memory")
#define CP_WAIT0()  asm volatile("cp.async.wait_group 0;" ::: "memory")

// Generic fp16 split-MMA over one 32-wide K chunk.
// Product order: P0=(a0,b0), P1=(a1,b0), P2=(a0,b1); nprod = prefix length.
template <int MI>
__device__ __forceinline__ void mma_terms(uint32_t a0, uint32_t a1,
                                          uint32_t b0, uint32_t b1, int nprod,
                                          int wm, int wn, int lane, float (*acc)[8][4])
{
    const int TAc[3] = {0, 1, 0};
    const int TBc[3] = {0, 0, 1};
#pragma unroll
    for (int ks = 0; ks < 2; ks++) {
        const uint32_t kb = ks * 32;
        const uint32_t a_row = (uint32_t)((wm + (lane & 15)) * 64) + kb + (lane >> 4) * 16;
        const uint32_t b_row = (uint32_t)((wn + (lane & 7) + ((lane >> 4) & 1) * 8) * 64) +
                               kb + ((lane >> 3) & 1) * 16;
#pragma unroll
        for (int p = 0; p < 3; p++) {
            if (p >= nprod) continue;
            const uint32_t ab = TAc[p] ? a1 : a0;
            const uint32_t bb = TBc[p] ? b1 : b0;
            uint32_t af4[MI][4];
#pragma unroll
            for (int mi = 0; mi < MI; mi++)
                ldsm_x4(af4[mi][0], af4[mi][1], af4[mi][2], af4[mi][3],
                        ab + sw64(a_row + (uint32_t)(mi * 16 * 64)));
#pragma unroll
            for (int nj = 0; nj < 4; nj++) {
                uint32_t b4[4];
                ldsm_x4(b4[0], b4[1], b4[2], b4[3],
                        bb + sw64(b_row + (uint32_t)(nj * 16 * 64)));
#pragma unroll
                for (int mi = 0; mi < MI; mi++) {
                    mma_h(acc[mi][2 * nj], af4[mi][0], af4[mi][1], af4[mi][2], af4[mi][3],
                          b4[0], b4[1]);
                    mma_h(acc[mi][2 * nj + 1], af4[mi][0], af4[mi][1], af4[mi][2], af4[mi][3],
                          b4[2], b4[3]);
                }
            }
        }
    }
}

// ---------------------------------------------------------------------------
// Kernel 0: weights: transpose, scale x64 (avoid fp16 subnormals), 2-term split
// ---------------------------------------------------------------------------
__global__ void wprep_kernel(const float* __restrict__ Wk,
                             const float* __restrict__ Wq,
                             const float* __restrict__ Wv)
{
    const float* W = (blockIdx.z == 0) ? Wk : (blockIdx.z == 1) ? Wq : Wv;
    __half* dst = g_Wt[blockIdx.z];
    __shared__ float tile[32][33];
    int k0 = blockIdx.x * 32, n0 = blockIdx.y * 32;
    int tx = threadIdx.x, ty = threadIdx.y;  // (32, 8)
#pragma unroll
    for (int i = 0; i < 32; i += 8)
        tile[ty + i][tx] = W[(size_t)(k0 + ty + i) * NH + n0 + tx];
    __syncthreads();
#pragma unroll
    for (int i = 0; i < 32; i += 8) {
        int n = n0 + ty + i, k = k0 + tx;
        float w = tile[tx][ty + i] * 64.0f;
        __half h1 = __float2half_rn(w);
        __half h2 = __float2half_rn(w - __half2float(h1));
        size_t o = (size_t)n * NC + k;
        dst[o] = h1;
        dst[(size_t)NH * NC + o] = h2;
    }
}

// ---------------------------------------------------------------------------
// Kernel 1: projection.  CTA tile 128x128, 2 CTAs/SM, warp tile 32x64.
// blockIdx.x = which*2 + ntile (fastest -> L2 reuse of X across 3 projections).
// K,Q: 3 products -> fp16 split pairs.  V: 2 products -> fp16.
// ---------------------------------------------------------------------------
#define PJ_STG 32768     // A0 8K | A1 8K | B0 8K | B1 8K
#define PJ_SMEM (2 * PJ_STG)

__global__ void __launch_bounds__(256, 2) proj_h_kernel(const float* __restrict__ X)
{
    extern __shared__ char sm[];
    const uint32_t smb = smem_u32(sm);
    const int tid = threadIdx.x, wid = tid >> 5, lane = tid & 31;
    const int wm = (wid >> 1) * 32, wn = (wid & 1) * 64;
    const int which = blockIdx.x >> 1, nt = blockIdx.x & 1;
    const int m0 = blockIdx.y * 128, n0 = nt * 128;
    const __half* Wp = g_Wt[which];
    const int nprod = (which == 2) ? 2 : 3;
    const int ar = tid >> 3, au = tid & 7;

    float acc[2][8][4] = {};

    auto load_x = [&](int c, float4* xv) {
        const float* Xp = X + (size_t)m0 * NC + (size_t)c * 32;
#pragma unroll
        for (int it = 0; it < 4; it++)
            xv[it] = *(const float4*)(Xp + (size_t)(ar + it * 32) * NC + au * 4);
    };
    auto store_a = [&](int buf, const float4* xv) {
#pragma unroll
        for (int it = 0; it < 4; it++) {
            __half x1 = __float2half_rn(xv[it].x), y1 = __float2half_rn(xv[it].y);
            __half z1 = __float2half_rn(xv[it].z), w1 = __float2half_rn(xv[it].w);
            __half x2 = __float2half_rn(xv[it].x - __half2float(x1));
            __half y2 = __float2half_rn(xv[it].y - __half2float(y1));
            __half z2 = __float2half_rn(xv[it].z - __half2float(z1));
            __half w2 = __float2half_rn(xv[it].w - __half2float(w1));
            uint32_t off = sw64((uint32_t)((ar + it * 32) * 64 + au * 8));
            *(uint2*)(sm + buf * PJ_STG + off) =
                make_uint2((uint32_t)__half_as_ushort(x1) | ((uint32_t)__half_as_ushort(y1) << 16),
                           (uint32_t)__half_as_ushort(z1) | ((uint32_t)__half_as_ushort(w1) << 16));
            *(uint2*)(sm + buf * PJ_STG + 8192 + off) =
                make_uint2((uint32_t)__half_as_ushort(x2) | ((uint32_t)__half_as_ushort(y2) << 16),
                           (uint32_t)__half_as_ushort(z2) | ((uint32_t)__half_as_ushort(w2) << 16));
        }
    };
    auto issue_b = [&](int c, int buf) {
#pragma unroll
        for (int it = 0; it < 4; it++) {
            int idx = tid + it * 256;      // 1024 granules: 2 terms x 128 rows x 4
            int t = idx >> 9, rem = idx & 511;
            int n = rem >> 2, u = rem & 3;
            cp_async16(smb + buf * PJ_STG + 16384 + t * 8192 + sw64((uint32_t)(n * 64 + u * 16)),
                       Wp + (size_t)t * NH * NC + (size_t)(n0 + n) * NC + (size_t)c * 32 + u * 8);
        }
        CP_COMMIT();
    };

    {
        float4 xv[4];
        load_x(0, xv);
        issue_b(0, 0);
        store_a(0, xv);
        CP_WAIT0();
        __syncthreads();
    }

    const int KT = NC / 32;   // 64
    for (int c = 0; c < KT; c++) {
        const int cur = c & 1;
        float4 xv[4];
        if (c + 1 < KT) {
            issue_b(c + 1, cur ^ 1);
            load_x(c + 1, xv);
        }
        mma_terms<2>(smb + cur * PJ_STG, smb + cur * PJ_STG + 8192,
                     smb + cur * PJ_STG + 16384, smb + cur * PJ_STG + 24576,
                     nprod, wm, wn, lane, acc);
        if (c + 1 < KT) {
            store_a(cur ^ 1, xv);
            CP_WAIT0();
        }
        __syncthreads();
    }

    const float inv = 1.0f / 64.0f;   // undo W prescale
    if (which == 2) {
#pragma unroll
        for (int mi = 0; mi < 2; mi++) {
            int m = m0 + wm + mi * 16 + (lane >> 2);
#pragma unroll
            for (int jj = 0; jj < 8; jj++) {
                int n = n0 + wn + jj * 8 + (lane & 3) * 2;
                *(__half2*)(g_Vh + (size_t)m * NH + n) =
                    __halves2half2(__float2half_rn(acc[mi][jj][0] * inv),
                                   __float2half_rn(acc[mi][jj][1] * inv));
                *(__half2*)(g_Vh + (size_t)(m + 8) * NH + n) =
                    __halves2half2(__float2half_rn(acc[mi][jj][2] * inv),
                                   __float2half_rn(acc[mi][jj][3] * inv));
            }
        }
    } else {
        __half* H1 = (which == 0) ? g_Kh[0] : g_Qh[0];
        __half* H2 = (which == 0) ? g_Kh[1] : g_Qh[1];
        auto store2 = [&](int m, int n, float a, float b) {
            __half a1 = __float2half_rn(a), b1 = __float2half_rn(b);
            __half a2 = __float2half_rn(a - __half2float(a1));
            __half b2 = __float2half_rn(b - __half2float(b1));
            *(__half2*)(H1 + (size_t)m * NH + n) = __halves2half2(a1, b1);
            *(__half2*)(H2 + (size_t)m * NH + n) = __halves2half2(a2, b2);
        };
#pragma unroll
        for (int mi = 0; mi < 2; mi++) {
            int m = m0 + wm + mi * 16 + (lane >> 2);
#pragma unroll
            for (int jj = 0; jj < 8; jj++) {
                int n = n0 + wn + jj * 8 + (lane & 3) * 2;
                store2(m, n, acc[mi][jj][0] * inv, acc[mi][jj][1] * inv);
                store2(m + 8, n, acc[mi][jj][2] * inv, acc[mi][jj][3] * inv);
            }
        }
    }
}

// ---------------------------------------------------------------------------
// Kernel 1b: V transpose: g_Vth[b][h][j] = g_Vh[b*NT+j][h]
// ---------------------------------------------------------------------------
__global__ void vtrans_kernel()
{
    __shared__ __half t[32][33];
    int b = blockIdx.z, j0 = blockIdx.x * 32, h0 = blockIdx.y * 32;
    int tx = threadIdx.x, ty = threadIdx.y;   // (32, 8)
    const __half* src = g_Vh + ((size_t)b * NT + j0) * NH + h0;
#pragma unroll
    for (int i = 0; i < 4; i++)
        t[ty + i * 8][tx] = src[(size_t)(ty + i * 8) * NH + tx];
    __syncthreads();
    __half* dst = g_Vth + ((size_t)b * NH + h0) * NT + j0;
#pragma unroll
    for (int i = 0; i < 4; i++)
        dst[(size_t)(ty + i * 8) * NT + tx] = t[tx][ty + i * 8];
}

// ---------------------------------------------------------------------------
// Kernel 2: logits + partial softmax stats.
// L[b][i][j] = sqrt(C) * K[b][i].Q[b][j].  Tile M=128 (i) x N=256 (j), K=256.
// Each warp-slab (64 i-rows) reduces per-column (max, sum) into g_pm/g_ps.
// ---------------------------------------------------------------------------
#define A_T 8192
#define B_T 16384
#define STG (2 * A_T + 2 * B_T)     // 49152
#define GEMM_SMEM (2 * STG)
__device__ __forceinline__ uint32_t a_off(int buf, int t) { return buf * STG + t * A_T; }
__device__ __forceinline__ uint32_t b_off(int buf, int t) { return buf * STG + 2 * A_T + t * B_T; }

__global__ void __launch_bounds__(256, 1) logits_h_kernel()
{
    const int bx = blockIdx.x, by = blockIdx.y, b = blockIdx.z;
    if (bx * 128 + 128 <= by * 256) return;   // all i < j: fully masked, never read
    const int i0 = bx * 128;
    const int j0 = by * 256;
    const size_t rowb = (size_t)b * NT;

    extern __shared__ char sm[];
    const uint32_t smb = smem_u32(sm);
    const int tid = threadIdx.x;
    const int wid = tid >> 5, lane = tid & 31;
    const int wr = wid >> 2, wc = wid & 3;
    const int wm = wr * 64, wn = wc * 64;

    float acc[4][8][4] = {};

    auto issue_a = [&](int c, int buf) {
#pragma unroll
        for (int it = 0; it < 4; it++) {
            int idx = tid + it * 256;
            int t = idx >> 9, rem = idx & 511;
            int r = rem >> 2, u = rem & 3;
            cp_async16(smb + a_off(buf, t) + sw64((uint32_t)(r * 64 + u * 16)),
                       g_Kh[t] + (rowb + i0 + r) * NH + (size_t)c * 32 + u * 8);
        }
    };
    auto issue_b = [&](int c, int buf) {
#pragma unroll
        for (int it = 0; it < 8; it++) {
            int idx = tid + it * 256;
            int t = idx >> 10, rem = idx & 1023;
            int n = rem >> 2, u = rem & 3;
            cp_async16(smb + b_off(buf, t) + sw64((uint32_t)(n * 64 + u * 16)),
                       g_Qh[t] + (rowb + j0 + n) * NH + (size_t)c * 32 + u * 8);
        }
    };

    issue_a(0, 0);
    issue_b(0, 0);
    CP_COMMIT();
    CP_WAIT0();
    __syncthreads();

    const int KT = NH / 32;   // 8
    for (int c = 0; c < KT; c++) {
        const int cur = c & 1;
        if (c + 1 < KT) {
            issue_a(c + 1, cur ^ 1);
            issue_b(c + 1, cur ^ 1);
            CP_COMMIT();
        }
        mma_terms<4>(smb + a_off(cur, 0), smb + a_off(cur, 1),
                     smb + b_off(cur, 0), smb + b_off(cur, 1),
                     3, wm, wn, lane, acc);
        if (c + 1 < KT) CP_WAIT0();
        __syncthreads();
    }

    const float scale = 45.25483399593904f;  // sqrt(2048)
    float* Lb = g_L + (size_t)b * NT * NT;
#pragma unroll
    for (int mi = 0; mi < 4; mi++) {
        int m = wm + mi * 16 + (lane >> 2);
#pragma unroll
        for (int jj = 0; jj < 8; jj++) {
            int n = wn + jj * 8 + (lane & 3) * 2;
            int jg = j0 + n;
            {
                int ig = i0 + m;
                float2 v;
                v.x = (ig >= jg) ? acc[mi][jj][0] * scale : -INFINITY;
                v.y = (ig >= jg + 1) ? acc[mi][jj][1] * scale : -INFINITY;
                *(float2*)(Lb + (size_t)ig * NT + jg) = v;
            }
            {
                int ig = i0 + m + 8;
                float2 v;
                v.x = (ig >= jg) ? acc[mi][jj][2] * scale : -INFINITY;
                v.y = (ig >= jg + 1) ? acc[mi][jj][3] * scale : -INFINITY;
                *(float2*)(Lb + (size_t)ig * NT + jg) = v;
            }
        }
    }

    // ---- partial softmax stats: per-column (max, sum) over this warp's 64 rows
    {
        const int bi2 = bx * 2 + wr;
        float* pmrow = g_pm + ((size_t)b * 32 + bi2) * NT;
        float* psrow = g_ps + ((size_t)b * 32 + bi2) * NT;
#pragma unroll
        for (int jj = 0; jj < 8; jj++) {
#pragma unroll
            for (int q = 0; q < 2; q++) {
                int jg = j0 + wn + jj * 8 + (lane & 3) * 2 + q;
                float v[8];
#pragma unroll
                for (int mi = 0; mi < 4; mi++) {
                    int ig = i0 + wm + mi * 16 + (lane >> 2);
                    v[2 * mi]     = (ig >= jg)     ? acc[mi][jj][q] * scale     : -INFINITY;
                    v[2 * mi + 1] = (ig + 8 >= jg) ? acc[mi][jj][q + 2] * scale : -INFINITY;
                }
                float mc = v[0];
#pragma unroll
                for (int k = 1; k < 8; k++) mc = fmaxf(mc, v[k]);
#pragma unroll
                for (int o = 4; o <= 16; o <<= 1)
                    mc = fmaxf(mc, __shfl_xor_sync(0xffffffffu, mc, o));
                float s = 0.f;
#pragma unroll
                for (int k = 0; k < 8; k++)
                    if (v[k] != -INFINITY) s += __expf(v[k] - mc);
#pragma unroll
                for (int o = 4; o <= 16; o <<= 1)
                    s += __shfl_xor_sync(0xffffffffu, s, o);
                if ((lane >> 2) == 0) { pmrow[jg] = mc; psrow[jg] = s; }
            }
        }
    }
}

// ---------------------------------------------------------------------------
// Kernel 3: combine partial stats -> g_m, g_rs.
// Valid slabs for column j: bi2 >= 4*(j>>8) (exactly the blocks that ran).
// ---------------------------------------------------------------------------
__global__ void __launch_bounds__(128) combine_kernel()
{
    const int j = blockIdx.x * 128 + threadIdx.x;
    const int b = blockIdx.y;
    const int k0 = (j >> 8) * 4;
    const float* pm = g_pm + (size_t)b * 32 * NT;
    const float* ps = g_ps + (size_t)b * 32 * NT;
    float m = -INFINITY;
    for (int k = k0; k < 32; k++) m = fmaxf(m, pm[(size_t)k * NT + j]);
    float s = 0.f;
    for (int k = k0; k < 32; k++) {
        float p = pm[(size_t)k * NT + j];
        if (p != -INFINITY) s += ps[(size_t)k * NT + j] * __expf(p - m);
    }
    g_m[b * NT + j] = m;
    g_rs[b * NT + j] = 1.0f / s;
}

// ---------------------------------------------------------------------------
// Kernel 4: av (fp16 MMA).  out[b][i][h] = sum_{j<=i} P[i][j] * V[j][h]
// Tile M=64 (i) x N=256 (h), 2 CTAs/SM, warp tile 32x64, exp fused in loader.
// ---------------------------------------------------------------------------
#define AV_STG 20480     // A 4K | B 16K
#define AV_SMEM (2 * AV_STG)

__global__ void __launch_bounds__(256, 2) av_h_kernel(float* __restrict__ Out)
{
    extern __shared__ char sm[];
    const uint32_t smb = smem_u32(sm);
    const int tid = threadIdx.x;
    const int wid = tid >> 5, lane = tid & 31;
    const int wm = (wid >> 2) * 32, wn = (wid & 3) * 64;
    const int b = blockIdx.y;
    const int i0 = (gridDim.x - 1 - blockIdx.x) * 64;   // big tiles first
    const float* Lb = g_L + (size_t)b * NT * NT;
    const float* mb = g_m + b * NT;
    const float* rb = g_rs + b * NT;
    const __half* Vt = g_Vth + (size_t)b * NH * NT;
    const int ar = tid >> 3, au = tid & 7;

    float acc[2][8][4] = {};

    auto load_p = [&](int c, float4* lv, float4& m4, float4& r4) {
        m4 = *(const float4*)(mb + c * 32 + au * 4);
        r4 = *(const float4*)(rb + c * 32 + au * 4);
#pragma unroll
        for (int it = 0; it < 2; it++)
            lv[it] = *(const float4*)(Lb + (size_t)(i0 + ar + it * 32) * NT +
                                      (size_t)c * 32 + au * 4);
    };
    auto store_p = [&](int buf, const float4* lv, const float4& m4, const float4& r4) {
#pragma unroll
        for (int it = 0; it < 2; it++) {
            __half px = __float2half_rn(__expf(lv[it].x - m4.x) * r4.x);
            __half py = __float2half_rn(__expf(lv[it].y - m4.y) * r4.y);
            __half pz = __float2half_rn(__expf(lv[it].z - m4.z) * r4.z);
            __half pw = __float2half_rn(__expf(lv[it].w - m4.w) * r4.w);
            uint32_t off = sw64((uint32_t)((ar + it * 32) * 64 + au * 8));
            *(uint2*)(sm + buf * AV_STG + off) =
                make_uint2((uint32_t)__half_as_ushort(px) | ((uint32_t)__half_as_ushort(py) << 16),
                           (uint32_t)__half_as_ushort(pz) | ((uint32_t)__half_as_ushort(pw) << 16));
        }
    };
    auto issue_v = [&](int c, int buf) {
#pragma unroll
        for (int it = 0; it < 4; it++) {
            int idx = tid + it * 256;      // 1024 granules: 256 rows x 4
            int n = idx >> 2, u = idx & 3;
            cp_async16(smb + buf * AV_STG + 4096 + sw64((uint32_t)(n * 64 + u * 16)),
                       Vt + (size_t)n * NT + (size_t)c * 32 + u * 8);
        }
        CP_COMMIT();
    };

    const int KT = (i0 + 64) / 32;

    {
        float4 lv[2], m4, r4;
        load_p(0, lv, m4, r4);
        issue_v(0, 0);
        store_p(0, lv, m4, r4);
        CP_WAIT0();
        __syncthreads();
    }

    for (int c = 0; c < KT; c++) {
        const int cur = c & 1;
        float4 lv[2], m4, r4;
        if (c + 1 < KT) {
            issue_v(c + 1, cur ^ 1);
            load_p(c + 1, lv, m4, r4);
        }
        mma_terms<2>(smb + cur * AV_STG, smb + cur * AV_STG,
                     smb + cur * AV_STG + 4096, smb + cur * AV_STG + 4096,
                     1, wm, wn, lane, acc);
        if (c + 1 < KT) {
            store_p(cur ^ 1, lv, m4, r4);
            CP_WAIT0();
        }
        __syncthreads();
    }

    float* Ob = Out + (size_t)b * NT * NH;
#pragma unroll
    for (int mi = 0; mi < 2; mi++) {
        int m = i0 + wm + mi * 16 + (lane >> 2);
#pragma unroll
        for (int jj = 0; jj < 8; jj++) {
            int n = wn + jj * 8 + (lane & 3) * 2;
            *(float2*)(Ob + (size_t)m * NH + n) = make_float2(acc[mi][jj][0], acc[mi][jj][1]);
            *(float2*)(Ob + (size_t)(m + 8) * NH + n) = make_float2(acc[mi][jj][2], acc[mi][jj][3]);
        }
    }
}

// ---------------------------------------------------------------------------
extern "C" void kernel_launch(void* const* d_in, const int* in_sizes, int n_in,
                              void* d_out, int out_size)
{
    const float* X  = (const float*)d_in[0];   // token_embd [16,2048,2048]
    const float* Wk = (const float*)d_in[1];   // [2048,256]
    const float* Wq = (const float*)d_in[2];
    const float* Wv = (const float*)d_in[3];
    float* out = (float*)d_out;                // [16,2048,256] fp32

    cudaFuncSetAttribute(proj_h_kernel,
                         cudaFuncAttributeMaxDynamicSharedMemorySize, PJ_SMEM);
    cudaFuncSetAttribute(logits_h_kernel,
                         cudaFuncAttributeMaxDynamicSharedMemorySize, GEMM_SMEM);
    cudaFuncSetAttribute(av_h_kernel,
                         cudaFuncAttributeMaxDynamicSharedMemorySize, AV_SMEM);

    wprep_kernel<<<dim3(NC / 32, NH / 32, 3), dim3(32, 8)>>>(Wk, Wq, Wv);

    // x = which*2 + ntile (fastest) -> 6 consecutive blocks share one X tile in L2
    proj_h_kernel<<<dim3(6, BTOT / 128), 256, PJ_SMEM>>>(X);

    vtrans_kernel<<<dim3(NT / 32, NH / 32, NB), dim3(32, 8)>>>();

    logits_h_kernel<<<dim3(NT / 128, NT / 256, NB), 256, GEMM_SMEM>>>();

    combine_kernel<<<dim3(NT / 128, NB), 128>>>();

    av_h_kernel<<<dim3(NT / 64, NB), 256, AV_SMEM>>>(out);
}

// round 12
// speedup vs baseline: 3.7008x; 1.0603x over previous
#include <cuda_runtime.h>
#include <cuda_fp16.h>
#include <math.h>
#include <stdint.h>

#define NB 16
#define NT 2048
#define NC 2048
#define NH 256
#define BTOT (NB * NT)   // 32768 rows

// Scratch (device globals: allocation-free per harness rules)
__device__ float g_L[NB * NT * NT];         // 268 MB, L[b][i][j] = k_i . q_j * sqrt(C)
__device__ float g_m[BTOT];                 // per (b,j) column max
__device__ float g_rs[BTOT];                // per (b,j) 1/sum
__device__ float g_pm[NB * 32 * NT];        // partial col-max per 64-row slab
__device__ float g_ps[NB * 32 * NT];        // partial col-sum per 64-row slab
__device__ __half g_Wt[3][2 * NH * NC];     // W*64 transposed, 2-term split
__device__ __half g_Kh[2][BTOT * NH];       // K fp16 2-term split
__device__ __half g_Qh[2][BTOT * NH];       // Q fp16 2-term split
__device__ __half g_Vh[BTOT * NH];          // V fp16 [b*NT+j][h]
__device__ __half g_Vth[NB * NH * NT];      // V^T fp16 [b][h][j]

// ---------------------------------------------------------------------------
__device__ __forceinline__ uint32_t smem_u32(const void* p) {
    uint32_t a;
    asm("{ .reg .u64 t; cvta.to.shared.u64 t, %1; cvt.u32.u64 %0, t; }"
        : "=r"(a) : "l"(p));
    return a;
}
__device__ __forceinline__ uint32_t sw64(uint32_t o) { return o ^ ((o >> 3) & 0x30); }

__device__ __forceinline__ void ldsm_x4(uint32_t& r0, uint32_t& r1, uint32_t& r2,
                                        uint32_t& r3, uint32_t addr) {
    asm volatile("ldmatrix.sync.aligned.m8n8.x4.shared.b16 {%0,%1,%2,%3}, [%4];"
                 : "=r"(r0), "=r"(r1), "=r"(r2), "=r"(r3) : "r"(addr));
}
__device__ __forceinline__ void mma_h(float* d, uint32_t a0, uint32_t a1,
                                      uint32_t a2, uint32_t a3,
                                      uint32_t b0, uint32_t b1) {
    asm volatile(
        "mma.sync.aligned.m16n8k16.row.col.f32.f16.f16.f32 "
        "{%0,%1,%2,%3}, {%4,%5,%6,%7}, {%8,%9}, {%0,%1,%2,%3};"
        : "+f"(d[0]), "+f"(d[1]), "+f"(d[2]), "+f"(d[3])
        : "r"(a0), "r"(a1), "r"(a2), "r"(a3), "r"(b0), "r"(b1));
}
__device__ __forceinline__ void cp_async16(uint32_t dst, const void* src) {
    asm volatile("cp.async.cg.shared.global [%0], [%1], 16;"
                 :: "r"(dst), "l"(src) : "memory");
}
#define CP_COMMIT() asm volatile("cp.async.commit_group;" ::: "memory")
#define CP_WAIT0()  asm volatile("cp.async.wait_group 0;" ::: "memory")

// Generic fp16 split-MMA over one 32-wide K chunk.
// Product order: P0=(a0,b0), P1=(a1,b0), P2=(a0,b1); nprod = prefix length.
template <int MI>
__device__ __forceinline__ void mma_terms(uint32_t a0, uint32_t a1,
                                          uint32_t b0, uint32_t b1, int nprod,
                                          int wm, int wn, int lane, float (*acc)[8][4])
{
    const int TAc[3] = {0, 1, 0};
    const int TBc[3] = {0, 0, 1};
#pragma unroll
    for (int ks = 0; ks < 2; ks++) {
        const uint32_t kb = ks * 32;
        const uint32_t a_row = (uint32_t)((wm + (lane & 15)) * 64) + kb + (lane >> 4) * 16;
        const uint32_t b_row = (uint32_t)((wn + (lane & 7) + ((lane >> 4) & 1) * 8) * 64) +
                               kb + ((lane >> 3) & 1) * 16;
#pragma unroll
        for (int p = 0; p < 3; p++) {
            if (p >= nprod) continue;
            const uint32_t ab = TAc[p] ? a1 : a0;
            const uint32_t bb = TBc[p] ? b1 : b0;
            uint32_t af4[MI][4];
#pragma unroll
            for (int mi = 0; mi < MI; mi++)
                ldsm_x4(af4[mi][0], af4[mi][1], af4[mi][2], af4[mi][3],
                        ab + sw64(a_row + (uint32_t)(mi * 16 * 64)));
#pragma unroll
            for (int nj = 0; nj < 4; nj++) {
                uint32_t b4[4];
                ldsm_x4(b4[0], b4[1], b4[2], b4[3],
                        bb + sw64(b_row + (uint32_t)(nj * 16 * 64)));
#pragma unroll
                for (int mi = 0; mi < MI; mi++) {
                    mma_h(acc[mi][2 * nj], af4[mi][0], af4[mi][1], af4[mi][2], af4[mi][3],
                          b4[0], b4[1]);
                    mma_h(acc[mi][2 * nj + 1], af4[mi][0], af4[mi][1], af4[mi][2], af4[mi][3],
                          b4[2], b4[3]);
                }
            }
        }
    }
}

// ---------------------------------------------------------------------------
// Kernel 0: weights: transpose, scale x64 (avoid fp16 subnormals), 2-term split
// ---------------------------------------------------------------------------
__global__ void wprep_kernel(const float* __restrict__ Wk,
                             const float* __restrict__ Wq,
                             const float* __restrict__ Wv)
{
    const float* W = (blockIdx.z == 0) ? Wk : (blockIdx.z == 1) ? Wq : Wv;
    __half* dst = g_Wt[blockIdx.z];
    __shared__ float tile[32][33];
    int k0 = blockIdx.x * 32, n0 = blockIdx.y * 32;
    int tx = threadIdx.x, ty = threadIdx.y;  // (32, 8)
#pragma unroll
    for (int i = 0; i < 32; i += 8)
        tile[ty + i][tx] = W[(size_t)(k0 + ty + i) * NH + n0 + tx];
    __syncthreads();
#pragma unroll
    for (int i = 0; i < 32; i += 8) {
        int n = n0 + ty + i, k = k0 + tx;
        float w = tile[tx][ty + i] * 64.0f;
        __half h1 = __float2half_rn(w);
        __half h2 = __float2half_rn(w - __half2float(h1));
        size_t o = (size_t)n * NC + k;
        dst[o] = h1;
        dst[(size_t)NH * NC + o] = h2;
    }
}

// ---------------------------------------------------------------------------
// Kernel 1: projection.  4 warps (128 thr), CTA tile 128x128, warp tile 64x64,
// 2 CTAs/SM.  blockIdx.x = which*2 + ntile (fastest -> L2 reuse of X).
// K,Q: 3 products -> fp16 split pairs.  V: 2 products -> fp16.
// ---------------------------------------------------------------------------
#define PJ_STG 32768     // A0 8K | A1 8K | B0 8K | B1 8K
#define PJ_SMEM (2 * PJ_STG)

__global__ void __launch_bounds__(128, 2) proj_h_kernel(const float* __restrict__ X)
{
    extern __shared__ char sm[];
    const uint32_t smb = smem_u32(sm);
    const int tid = threadIdx.x, wid = tid >> 5, lane = tid & 31;
    const int wm = (wid >> 1) * 64, wn = (wid & 1) * 64;
    const int which = blockIdx.x >> 1, nt = blockIdx.x & 1;
    const int m0 = blockIdx.y * 128, n0 = nt * 128;
    const __half* Wp = g_Wt[which];
    const int nprod = (which == 2) ? 2 : 3;
    const int ar = tid >> 3, au = tid & 7;   // A loader: 16 rows x 8 f4-slots

    float acc[4][8][4] = {};

    auto load_x = [&](int c, float4* xv) {
        const float* Xp = X + (size_t)m0 * NC + (size_t)c * 32;
#pragma unroll
        for (int it = 0; it < 8; it++)
            xv[it] = *(const float4*)(Xp + (size_t)(ar + it * 16) * NC + au * 4);
    };
    auto store_a = [&](int buf, const float4* xv) {
#pragma unroll
        for (int it = 0; it < 8; it++) {
            __half x1 = __float2half_rn(xv[it].x), y1 = __float2half_rn(xv[it].y);
            __half z1 = __float2half_rn(xv[it].z), w1 = __float2half_rn(xv[it].w);
            __half x2 = __float2half_rn(xv[it].x - __half2float(x1));
            __half y2 = __float2half_rn(xv[it].y - __half2float(y1));
            __half z2 = __float2half_rn(xv[it].z - __half2float(z1));
            __half w2 = __float2half_rn(xv[it].w - __half2float(w1));
            uint32_t off = sw64((uint32_t)((ar + it * 16) * 64 + au * 8));
            *(uint2*)(sm + buf * PJ_STG + off) =
                make_uint2((uint32_t)__half_as_ushort(x1) | ((uint32_t)__half_as_ushort(y1) << 16),
                           (uint32_t)__half_as_ushort(z1) | ((uint32_t)__half_as_ushort(w1) << 16));
            *(uint2*)(sm + buf * PJ_STG + 8192 + off) =
                make_uint2((uint32_t)__half_as_ushort(x2) | ((uint32_t)__half_as_ushort(y2) << 16),
                           (uint32_t)__half_as_ushort(z2) | ((uint32_t)__half_as_ushort(w2) << 16));
        }
    };
    auto issue_b = [&](int c, int buf) {
#pragma unroll
        for (int it = 0; it < 8; it++) {
            int idx = tid + it * 128;      // 1024 granules: 2 terms x 128 rows x 4
            int t = idx >> 9, rem = idx & 511;
            int n = rem >> 2, u = rem & 3;
            cp_async16(smb + buf * PJ_STG + 16384 + t * 8192 + sw64((uint32_t)(n * 64 + u * 16)),
                       Wp + (size_t)t * NH * NC + (size_t)(n0 + n) * NC + (size_t)c * 32 + u * 8);
        }
        CP_COMMIT();
    };

    {
        float4 xv[8];
        load_x(0, xv);
        issue_b(0, 0);
        store_a(0, xv);
        CP_WAIT0();
        __syncthreads();
    }

    const int KT = NC / 32;   // 64
    for (int c = 0; c < KT; c++) {
        const int cur = c & 1;
        float4 xv[8];
        if (c + 1 < KT) {
            issue_b(c + 1, cur ^ 1);
            load_x(c + 1, xv);
        }
        mma_terms<4>(smb + cur * PJ_STG, smb + cur * PJ_STG + 8192,
                     smb + cur * PJ_STG + 16384, smb + cur * PJ_STG + 24576,
                     nprod, wm, wn, lane, acc);
        if (c + 1 < KT) {
            store_a(cur ^ 1, xv);
            CP_WAIT0();
        }
        __syncthreads();
    }

    const float inv = 1.0f / 64.0f;   // undo W prescale
    if (which == 2) {
#pragma unroll
        for (int mi = 0; mi < 4; mi++) {
            int m = m0 + wm + mi * 16 + (lane >> 2);
#pragma unroll
            for (int jj = 0; jj < 8; jj++) {
                int n = n0 + wn + jj * 8 + (lane & 3) * 2;
                *(__half2*)(g_Vh + (size_t)m * NH + n) =
                    __halves2half2(__float2half_rn(acc[mi][jj][0] * inv),
                                   __float2half_rn(acc[mi][jj][1] * inv));
                *(__half2*)(g_Vh + (size_t)(m + 8) * NH + n) =
                    __halves2half2(__float2half_rn(acc[mi][jj][2] * inv),
                                   __float2half_rn(acc[mi][jj][3] * inv));
            }
        }
    } else {
        __half* H1 = (which == 0) ? g_Kh[0] : g_Qh[0];
        __half* H2 = (which == 0) ? g_Kh[1] : g_Qh[1];
        auto store2 = [&](int m, int n, float a, float b) {
            __half a1 = __float2half_rn(a), b1 = __float2half_rn(b);
            __half a2 = __float2half_rn(a - __half2float(a1));
            __half b2 = __float2half_rn(b - __half2float(b1));
            *(__half2*)(H1 + (size_t)m * NH + n) = __halves2half2(a1, b1);
            *(__half2*)(H2 + (size_t)m * NH + n) = __halves2half2(a2, b2);
        };
#pragma unroll
        for (int mi = 0; mi < 4; mi++) {
            int m = m0 + wm + mi * 16 + (lane >> 2);
#pragma unroll
            for (int jj = 0; jj < 8; jj++) {
                int n = n0 + wn + jj * 8 + (lane & 3) * 2;
                store2(m, n, acc[mi][jj][0] * inv, acc[mi][jj][1] * inv);
                store2(m + 8, n, acc[mi][jj][2] * inv, acc[mi][jj][3] * inv);
            }
        }
    }
}

// ---------------------------------------------------------------------------
// Kernel 1b: V transpose: g_Vth[b][h][j] = g_Vh[b*NT+j][h]
// ---------------------------------------------------------------------------
__global__ void vtrans_kernel()
{
    __shared__ __half t[32][33];
    int b = blockIdx.z, j0 = blockIdx.x * 32, h0 = blockIdx.y * 32;
    int tx = threadIdx.x, ty = threadIdx.y;   // (32, 8)
    const __half* src = g_Vh + ((size_t)b * NT + j0) * NH + h0;
#pragma unroll
    for (int i = 0; i < 4; i++)
        t[ty + i * 8][tx] = src[(size_t)(ty + i * 8) * NH + tx];
    __syncthreads();
    __half* dst = g_Vth + ((size_t)b * NH + h0) * NT + j0;
#pragma unroll
    for (int i = 0; i < 4; i++)
        dst[(size_t)(ty + i * 8) * NT + tx] = t[tx][ty + i * 8];
}

// ---------------------------------------------------------------------------
// Kernel 2: logits + partial softmax stats.
// L[b][i][j] = sqrt(C) * K[b][i].Q[b][j].  Tile 128 (i) x 128 (j), K=256.
// 4 warps (128 thr), warp tile 64x64, 2 CTAs/SM.
// Each warp-slab (64 i-rows) reduces per-column (max, sum) into g_pm/g_ps.
// ---------------------------------------------------------------------------
#define LG_STG 32768     // A0 8K | A1 8K | B0 8K | B1 8K
#define LG_SMEM (2 * LG_STG)

__global__ void __launch_bounds__(128, 2) logits_h_kernel()
{
    const int bx = blockIdx.x, by = blockIdx.y, b = blockIdx.z;
    if (bx < by) return;                      // all i < j: fully masked, never read
    const int i0 = bx * 128;
    const int j0 = by * 128;
    const size_t rowb = (size_t)b * NT;

    extern __shared__ char sm[];
    const uint32_t smb = smem_u32(sm);
    const int tid = threadIdx.x;
    const int wid = tid >> 5, lane = tid & 31;
    const int wr = wid >> 1, wc = wid & 1;
    const int wm = wr * 64, wn = wc * 64;

    float acc[4][8][4] = {};

    auto issue_a = [&](int c, int buf) {
#pragma unroll
        for (int it = 0; it < 8; it++) {
            int idx = tid + it * 128;      // 1024: 2 terms x 128 rows x 4
            int t = idx >> 9, rem = idx & 511;
            int r = rem >> 2, u = rem & 3;
            cp_async16(smb + buf * LG_STG + t * 8192 + sw64((uint32_t)(r * 64 + u * 16)),
                       g_Kh[t] + (rowb + i0 + r) * NH + (size_t)c * 32 + u * 8);
        }
    };
    auto issue_b = [&](int c, int buf) {
#pragma unroll
        for (int it = 0; it < 8; it++) {
            int idx = tid + it * 128;
            int t = idx >> 9, rem = idx & 511;
            int n = rem >> 2, u = rem & 3;
            cp_async16(smb + buf * LG_STG + 16384 + t * 8192 + sw64((uint32_t)(n * 64 + u * 16)),
                       g_Qh[t] + (rowb + j0 + n) * NH + (size_t)c * 32 + u * 8);
        }
    };

    issue_a(0, 0);
    issue_b(0, 0);
    CP_COMMIT();
    CP_WAIT0();
    __syncthreads();

    const int KT = NH / 32;   // 8
    for (int c = 0; c < KT; c++) {
        const int cur = c & 1;
        if (c + 1 < KT) {
            issue_a(c + 1, cur ^ 1);
            issue_b(c + 1, cur ^ 1);
            CP_COMMIT();
        }
        mma_terms<4>(smb + cur * LG_STG, smb + cur * LG_STG + 8192,
                     smb + cur * LG_STG + 16384, smb + cur * LG_STG + 24576,
                     3, wm, wn, lane, acc);
        if (c + 1 < KT) CP_WAIT0();
        __syncthreads();
    }

    const float scale = 45.25483399593904f;  // sqrt(2048)
    float* Lb = g_L + (size_t)b * NT * NT;
#pragma unroll
    for (int mi = 0; mi < 4; mi++) {
        int m = wm + mi * 16 + (lane >> 2);
#pragma unroll
        for (int jj = 0; jj < 8; jj++) {
            int n = wn + jj * 8 + (lane & 3) * 2;
            int jg = j0 + n;
            {
                int ig = i0 + m;
                float2 v;
                v.x = (ig >= jg) ? acc[mi][jj][0] * scale : -INFINITY;
                v.y = (ig >= jg + 1) ? acc[mi][jj][1] * scale : -INFINITY;
                *(float2*)(Lb + (size_t)ig * NT + jg) = v;
            }
            {
                int ig = i0 + m + 8;
                float2 v;
                v.x = (ig >= jg) ? acc[mi][jj][2] * scale : -INFINITY;
                v.y = (ig >= jg + 1) ? acc[mi][jj][3] * scale : -INFINITY;
                *(float2*)(Lb + (size_t)ig * NT + jg) = v;
            }
        }
    }

    // ---- partial softmax stats: per-column (max, sum) over this warp's 64 rows
    {
        const int bi2 = bx * 2 + wr;
        float* pmrow = g_pm + ((size_t)b * 32 + bi2) * NT;
        float* psrow = g_ps + ((size_t)b * 32 + bi2) * NT;
#pragma unroll
        for (int jj = 0; jj < 8; jj++) {
#pragma unroll
            for (int q = 0; q < 2; q++) {
                int jg = j0 + wn + jj * 8 + (lane & 3) * 2 + q;
                float v[8];
#pragma unroll
                for (int mi = 0; mi < 4; mi++) {
                    int ig = i0 + wm + mi * 16 + (lane >> 2);
                    v[2 * mi]     = (ig >= jg)     ? acc[mi][jj][q] * scale     : -INFINITY;
                    v[2 * mi + 1] = (ig + 8 >= jg) ? acc[mi][jj][q + 2] * scale : -INFINITY;
                }
                float mc = v[0];
#pragma unroll
                for (int k = 1; k < 8; k++) mc = fmaxf(mc, v[k]);
#pragma unroll
                for (int o = 4; o <= 16; o <<= 1)
                    mc = fmaxf(mc, __shfl_xor_sync(0xffffffffu, mc, o));
                float s = 0.f;
#pragma unroll
                for (int k = 0; k < 8; k++)
                    if (v[k] != -INFINITY) s += __expf(v[k] - mc);
#pragma unroll
                for (int o = 4; o <= 16; o <<= 1)
                    s += __shfl_xor_sync(0xffffffffu, s, o);
                if ((lane >> 2) == 0) { pmrow[jg] = mc; psrow[jg] = s; }
            }
        }
    }
}

// ---------------------------------------------------------------------------
// Kernel 3: combine partial stats -> g_m, g_rs.
// Valid slabs for column j: bi2 >= 2*(j>>7) (exactly the blocks that ran).
// ---------------------------------------------------------------------------
__global__ void __launch_bounds__(128) combine_kernel()
{
    const int j = blockIdx.x * 128 + threadIdx.x;
    const int b = blockIdx.y;
    const int k0 = (j >> 7) * 2;
    const float* pm = g_pm + (size_t)b * 32 * NT;
    const float* ps = g_ps + (size_t)b * 32 * NT;
    float m = -INFINITY;
    for (int k = k0; k < 32; k++) m = fmaxf(m, pm[(size_t)k * NT + j]);
    float s = 0.f;
    for (int k = k0; k < 32; k++) {
        float p = pm[(size_t)k * NT + j];
        if (p != -INFINITY) s += ps[(size_t)k * NT + j] * __expf(p - m);
    }
    g_m[b * NT + j] = m;
    g_rs[b * NT + j] = 1.0f / s;
}

// ---------------------------------------------------------------------------
// Kernel 4: av (fp16 MMA).  out[b][i][h] = sum_{j<=i} P[i][j] * V[j][h]
// Tile M=64 (i) x N=256 (h), 2 CTAs/SM, warp tile 32x64, exp fused in loader.
// ---------------------------------------------------------------------------
#define AV_STG 20480     // A 4K | B 16K
#define AV_SMEM (2 * AV_STG)

__global__ void __launch_bounds__(256, 2) av_h_kernel(float* __restrict__ Out)
{
    extern __shared__ char sm[];
    const uint32_t smb = smem_u32(sm);
    const int tid = threadIdx.x;
    const int wid = tid >> 5, lane = tid & 31;
    const int wm = (wid >> 2) * 32, wn = (wid & 3) * 64;
    const int b = blockIdx.y;
    const int i0 = (gridDim.x - 1 - blockIdx.x) * 64;   // big tiles first
    const float* Lb = g_L + (size_t)b * NT * NT;
    const float* mb = g_m + b * NT;
    const float* rb = g_rs + b * NT;
    const __half* Vt = g_Vth + (size_t)b * NH * NT;
    const int ar = tid >> 3, au = tid & 7;

    float acc[2][8][4] = {};

    auto load_p = [&](int c, float4* lv, float4& m4, float4& r4) {
        m4 = *(const float4*)(mb + c * 32 + au * 4);
        r4 = *(const float4*)(rb + c * 32 + au * 4);
#pragma unroll
        for (int it = 0; it < 2; it++)
            lv[it] = *(const float4*)(Lb + (size_t)(i0 + ar + it * 32) * NT +
                                      (size_t)c * 32 + au * 4);
    };
    auto store_p = [&](int buf, const float4* lv, const float4& m4, const float4& r4) {
#pragma unroll
        for (int it = 0; it < 2; it++) {
            __half px = __float2half_rn(__expf(lv[it].x - m4.x) * r4.x);
            __half py = __float2half_rn(__expf(lv[it].y - m4.y) * r4.y);
            __half pz = __float2half_rn(__expf(lv[it].z - m4.z) * r4.z);
            __half pw = __float2half_rn(__expf(lv[it].w - m4.w) * r4.w);
            uint32_t off = sw64((uint32_t)((ar + it * 32) * 64 + au * 8));
            *(uint2*)(sm + buf * AV_STG + off) =
                make_uint2((uint32_t)__half_as_ushort(px) | ((uint32_t)__half_as_ushort(py) << 16),
                           (uint32_t)__half_as_ushort(pz) | ((uint32_t)__half_as_ushort(pw) << 16));
        }
    };
    auto issue_v = [&](int c, int buf) {
#pragma unroll
        for (int it = 0; it < 4; it++) {
            int idx = tid + it * 256;      // 1024 granules: 256 rows x 4
            int n = idx >> 2, u = idx & 3;
            cp_async16(smb + buf * AV_STG + 4096 + sw64((uint32_t)(n * 64 + u * 16)),
                       Vt + (size_t)n * NT + (size_t)c * 32 + u * 8);
        }
        CP_COMMIT();
    };

    const int KT = (i0 + 64) / 32;

    {
        float4 lv[2], m4, r4;
        load_p(0, lv, m4, r4);
        issue_v(0, 0);
        store_p(0, lv, m4, r4);
        CP_WAIT0();
        __syncthreads();
    }

    for (int c = 0; c < KT; c++) {
        const int cur = c & 1;
        float4 lv[2], m4, r4;
        if (c + 1 < KT) {
            issue_v(c + 1, cur ^ 1);
            load_p(c + 1, lv, m4, r4);
        }
        mma_terms<2>(smb + cur * AV_STG, smb + cur * AV_STG,
                     smb + cur * AV_STG + 4096, smb + cur * AV_STG + 4096,
                     1, wm, wn, lane, acc);
        if (c + 1 < KT) {
            store_p(cur ^ 1, lv, m4, r4);
            CP_WAIT0();
        }
        __syncthreads();
    }

    float* Ob = Out + (size_t)b * NT * NH;
#pragma unroll
    for (int mi = 0; mi < 2; mi++) {
        int m = i0 + wm + mi * 16 + (lane >> 2);
#pragma unroll
        for (int jj = 0; jj < 8; jj++) {
            int n = wn + jj * 8 + (lane & 3) * 2;
            *(float2*)(Ob + (size_t)m * NH + n) = make_float2(acc[mi][jj][0], acc[mi][jj][1]);
            *(float2*)(Ob + (size_t)(m + 8) * NH + n) = make_float2(acc[mi][jj][2], acc[mi][jj][3]);
        }
    }
}

// ---------------------------------------------------------------------------
extern "C" void kernel_launch(void* const* d_in, const int* in_sizes, int n_in,
                              void* d_out, int out_size)
{
    const float* X  = (const float*)d_in[0];   // token_embd [16,2048,2048]
    const float* Wk = (const float*)d_in[1];   // [2048,256]
    const float* Wq = (const float*)d_in[2];
    const float* Wv = (const float*)d_in[3];
    float* out = (float*)d_out;                // [16,2048,256] fp32

    cudaFuncSetAttribute(proj_h_kernel,
                         cudaFuncAttributeMaxDynamicSharedMemorySize, PJ_SMEM);
    cudaFuncSetAttribute(logits_h_kernel,
                         cudaFuncAttributeMaxDynamicSharedMemorySize, LG_SMEM);
    cudaFuncSetAttribute(av_h_kernel,
                         cudaFuncAttributeMaxDynamicSharedMemorySize, AV_SMEM);

    wprep_kernel<<<dim3(NC / 32, NH / 32, 3), dim3(32, 8)>>>(Wk, Wq, Wv);

    // x = which*2 + ntile (fastest) -> 6 consecutive blocks share one X tile in L2
    proj_h_kernel<<<dim3(6, BTOT / 128), 128, PJ_SMEM>>>(X);

    vtrans_kernel<<<dim3(NT / 32, NH / 32, NB), dim3(32, 8)>>>();

    logits_h_kernel<<<dim3(NT / 128, NT / 128, NB), 128, LG_SMEM>>>();

    combine_kernel<<<dim3(NT / 128, NB), 128>>>();

    av_h_kernel<<<dim3(NT / 64, NB), 256, AV_SMEM>>>(out);
}